// round 13
// baseline (speedup 1.0000x reference)
#include <cuda_runtime.h>
#include <cuda_fp16.h>

#define NN 100000
#define NE 3200000
#define DD 64
#define EPSBN 1e-5f
#define NSM 148
#define NITEM ((NN + NSM - 1) / NSM)        // 676 items per block

// ---------------- scratch (no allocations allowed) ----------------
__device__ int    g_deg[NN];
__device__ int    g_off[NN + 1];
__device__ int    g_cursor[NN];
__device__ int    g_csum[NSM];
__device__ volatile int g_bar1;
__device__ volatile int g_bar2;
__device__ float  g_dinv[NN];
__device__ int2   g_entries[NE];           // {src, weight-bits}
__device__ __half g_hsrc[(size_t)NN * DD]; // half gather source (x, then y1)
__device__ float  g_agg[(size_t)NN * DD];
__device__ float  g_y[(size_t)NN * DD];
__device__ float  g_stats[4 * DD];         // [0..127] layer1, [128..255] layer2
__device__ float  g_wc[DD * DD];           // combined W@fw
__device__ float  g_bc[DD];                // combined bias

// ------- x -> half conversion (+ deg zero, + barrier reset, + histogram) ---
__global__ void k_x2h(const float* __restrict__ x, const int* __restrict__ dst) {
    int i = blockIdx.x * blockDim.x + threadIdx.x;
    int total = gridDim.x * blockDim.x;
    if (i < NN * DD / 4) {
        float4 v = reinterpret_cast<const float4*>(x)[i];
        __half2* o = reinterpret_cast<__half2*>(g_hsrc) + 2 * i;
        o[0] = __floats2half2_rn(v.x, v.y);
        o[1] = __floats2half2_rn(v.z, v.w);
    }
    if (i < NN) g_deg[i] = 0;
    if (i == 0) { g_bar1 = 0; g_bar2 = 0; }
    // NOTE: histogram must see zeroed g_deg. Zeroing above covers i<NN but other
    // blocks may histogram before block covering i zeroes it -> race. Avoid by
    // having EVERY thread zero before grid-wide use is impossible without a grid
    // barrier; instead run histogram in a second grid-stride phase gated on a
    // device barrier is overkill. Solution: zero in the PREVIOUS kernel is not
    // available on first launch, so we instead count into g_cursor (scratch,
    // zeroed here too is same race)... -> keep it simple: histogram runs here
    // only for edges, targeting g_deg zeroed by the HARNESS-ORDER trick below.
    // We sidestep the race by zeroing g_deg at the END of the final kernel of
    // the previous launch? Not valid (first call). => do histogram with a
    // separate counter array g_cursor zeroed LAST ROUND is also invalid.
    // Final resolution: histogram moved to k_scan_scatter phase 0 (pre-scan),
    // which starts after this kernel fully completes (stream order).
    (void)dst; (void)total;
}

// ---------------- fused hist + scan + scatter (one wave) -------------------
__device__ __forceinline__ void gbar(volatile int* bar, int target) {
    __syncthreads();
    if (threadIdx.x == 0) {
        __threadfence();
        atomicAdd((int*)bar, 1);
        while (*bar < target) { }
    }
    __syncthreads();
}

__global__ void __launch_bounds__(1024) k_scan_scatter(const int* __restrict__ src,
                                                       const int* __restrict__ dst) {
    __shared__ int sh[1024];
    __shared__ int s_base;
    int b = blockIdx.x, t = threadIdx.x;

    // phase 0: histogram (g_deg zeroed by k_x2h, complete via stream order)
    for (int e = b * 1024 + t; e < NE; e += NSM * 1024)
        atomicAdd(&g_deg[dst[e]], 1);

    gbar(&g_bar1, NSM);                     // all counts visible

    // phase 1: scan
    int i = b * NITEM + t;
    int val = (t < NITEM && i < NN) ? g_deg[i] : 0;
    sh[t] = val;
    __syncthreads();
    #pragma unroll
    for (int o = 1; o < 1024; o <<= 1) {
        int xv = (t >= o) ? sh[t - o] : 0;
        __syncthreads();
        sh[t] += xv;
        __syncthreads();
    }
    if (t == 1023) g_csum[b] = sh[1023];
    int locex = sh[t] - val;                // exclusive within block

    gbar(&g_bar2, NSM);                     // all csum visible

    if (t == 0) {
        int s = 0;
        for (int j = 0; j < b; j++) s += g_csum[j];
        s_base = s;
    }
    __syncthreads();
    if (t < NITEM && i < NN) {
        int v = s_base + locex;
        g_off[i] = v;
        g_cursor[i] = v;
        g_dinv[i] = rsqrtf((float)(val + 1));   // +1 self loop
    }
    if (b == NSM - 1 && t == 0) g_off[NN] = NE;

    gbar(&g_bar1, 2 * NSM);                 // all offsets/dinv visible (reuse bar1)

    // phase 2: scatter
    for (int e = b * 1024 + t; e < NE; e += NSM * 1024) {
        int s = src[e], d = dst[e];
        float w = g_dinv[s] * g_dinv[d];
        int pos = atomicAdd(&g_cursor[d], 1);
        g_entries[pos] = make_int2(s, __float_as_int(w));
    }
}

// ---------------- weight combine: Wc = W@fw, bc = b@fw + fb; zero stats ---
__global__ void k_combine(const float* __restrict__ W, const float* __restrict__ fw,
                          const float* __restrict__ b, const float* __restrict__ fb,
                          int statsBase) {
    int col = threadIdx.x;          // 0..63
    int rb  = threadIdx.y * 4;      // row base, y in 0..15
    float acc[4] = {0.f, 0.f, 0.f, 0.f};
    for (int k = 0; k < DD; k++) {
        float f = fw[k * DD + col];
        #pragma unroll
        for (int r = 0; r < 4; r++) acc[r] += W[(rb + r) * DD + k] * f;
    }
    #pragma unroll
    for (int r = 0; r < 4; r++) g_wc[(rb + r) * DD + col] = acc[r];
    if (threadIdx.y == 0) {
        float s = fb[col];
        for (int k = 0; k < DD; k++) s += b[k] * fw[k * DD + col];
        g_bc[col] = s;
    }
    if (threadIdx.y == 1) {
        g_stats[statsBase + col] = 0.f;
        g_stats[statsBase + 64 + col] = 0.f;
    }
}

// ---------------- helpers ----------------
__device__ __forceinline__ float4 h4f(uint2 r) {
    __half2 h0 = *reinterpret_cast<__half2*>(&r.x);
    __half2 h1 = *reinterpret_cast<__half2*>(&r.y);
    float2 f0 = __half22float2(h0);
    float2 f1 = __half22float2(h1);
    return make_float4(f0.x, f0.y, f1.x, f1.y);
}
__device__ __forceinline__ float4 bnr4(float4 v, float4 sc, float4 sh) {
    v.x = fmaxf(v.x * sc.x + sh.x, 0.f);
    v.y = fmaxf(v.y * sc.y + sh.y, 0.f);
    v.z = fmaxf(v.z * sc.z + sh.z, 0.f);
    v.w = fmaxf(v.w * sc.w + sh.w, 0.f);
    return v;
}

// ---------------- aggregation: gather over CSR (half rows), 16 thr/node ---
// paired int4 entry loads; 32-bit addressing throughout
__global__ void __launch_bounds__(256) k_agg(float* __restrict__ agg, int mode,
                                             const float* __restrict__ g,
                                             const float* __restrict__ bt) {
    __shared__ float s_sc[DD], s_sh[DD];
    if (mode == 2) {
        if (threadIdx.x < DD) {
            int c = threadIdx.x;
            float mu  = g_stats[c] * (1.0f / NN);
            float var = g_stats[64 + c] * (1.0f / NN) - mu * mu;
            float scv = g[c] * rsqrtf(var + EPSBN);
            s_sc[c] = scv;
            s_sh[c] = bt[c] - mu * scv;
        }
        __syncthreads();
    }

    int node = blockIdx.x * 16 + (threadIdx.x >> 4);
    int q = threadIdx.x & 15;                 // 8-byte (4-half) slice
    if (node >= NN) return;

    float4 sc = make_float4(1.f, 1.f, 1.f, 1.f);
    float4 sh = make_float4(0.f, 0.f, 0.f, 0.f);
    if (mode == 2) {
        sc = *reinterpret_cast<const float4*>(&s_sc[q * 4]);
        sh = *reinterpret_cast<const float4*>(&s_sh[q * 4]);
    }

    int beg = g_off[node];
    int end = g_off[node + 1];
    float di = g_dinv[node];
    float ww = di * di;

    const uint2* hs = reinterpret_cast<const uint2*>(g_hsrc);

    float4 a = h4f(hs[node * 16 + q]);        // 32-bit index (max 1.6M)
    if (mode == 2) a = bnr4(a, sc, sh);
    float4 acc = make_float4(ww * a.x, ww * a.y, ww * a.z, ww * a.w);

    int e = beg;
    if ((e & 1) && e < end) {                 // align to even for int4 pairs
        int2 e0 = g_entries[e];
        float w0 = __int_as_float(e0.y);
        float4 v0 = h4f(hs[e0.x * 16 + q]);
        if (mode == 2) v0 = bnr4(v0, sc, sh);
        acc.x += w0 * v0.x; acc.y += w0 * v0.y;
        acc.z += w0 * v0.z; acc.w += w0 * v0.w;
        e++;
    }
    for (; e + 4 <= end; e += 4) {
        int4 p0 = *reinterpret_cast<const int4*>(g_entries + e);      // e0,e1
        int4 p1 = *reinterpret_cast<const int4*>(g_entries + e + 2);  // e2,e3
        float4 v0 = h4f(hs[p0.x * 16 + q]);
        float4 v1 = h4f(hs[p0.z * 16 + q]);
        float4 v2 = h4f(hs[p1.x * 16 + q]);
        float4 v3 = h4f(hs[p1.z * 16 + q]);
        if (mode == 2) {
            v0 = bnr4(v0, sc, sh);
            v1 = bnr4(v1, sc, sh);
            v2 = bnr4(v2, sc, sh);
            v3 = bnr4(v3, sc, sh);
        }
        float w0 = __int_as_float(p0.y), w1 = __int_as_float(p0.w);
        float w2 = __int_as_float(p1.y), w3 = __int_as_float(p1.w);
        acc.x += w0 * v0.x + w1 * v1.x + w2 * v2.x + w3 * v3.x;
        acc.y += w0 * v0.y + w1 * v1.y + w2 * v2.y + w3 * v3.y;
        acc.z += w0 * v0.z + w1 * v1.z + w2 * v2.z + w3 * v3.z;
        acc.w += w0 * v0.w + w1 * v1.w + w2 * v2.w + w3 * v3.w;
    }
    for (; e < end; e++) {
        int2 e0 = g_entries[e];
        float w0 = __int_as_float(e0.y);
        float4 v0 = h4f(hs[e0.x * 16 + q]);
        if (mode == 2) v0 = bnr4(v0, sc, sh);
        acc.x += w0 * v0.x;
        acc.y += w0 * v0.y;
        acc.z += w0 * v0.z;
        acc.w += w0 * v0.w;
    }
    *reinterpret_cast<float4*>(agg + node * 64 + q * 4) = acc;
}

// ---------------- GEMM: in[N,64] @ g_wc + g_bc -> out (fp32 or half) ------
__global__ void __launch_bounds__(256) k_gemm(const float* __restrict__ in,
                                              float* __restrict__ out,
                                              __half* __restrict__ outh,
                                              int statsBase) {
    __shared__ float Xt[DD * 68];
    __shared__ float Ws[DD * DD];
    __shared__ float sred[2][4][DD];

    const int col = threadIdx.x;
    const int rg  = threadIdx.y;
    const int tid = rg * 64 + col;
    const int r0  = blockIdx.x * 64;

    #pragma unroll
    for (int it = 0; it < 4; it++) {
        int fi = (tid + it * 256) * 4;
        *reinterpret_cast<float4*>(&Ws[fi]) =
            *reinterpret_cast<const float4*>(&g_wc[fi]);
    }
    #pragma unroll
    for (int it = 0; it < 4; it++) {
        int fi = (tid + it * 256) * 4;
        int r = fi >> 6;
        int c = fi & 63;
        float4 v;
        if (r0 + r < NN)
            v = *reinterpret_cast<const float4*>(&in[(size_t)(r0 + r) * DD + c]);
        else
            v = make_float4(0.f, 0.f, 0.f, 0.f);
        Xt[(c + 0) * 68 + r] = v.x;
        Xt[(c + 1) * 68 + r] = v.y;
        Xt[(c + 2) * 68 + r] = v.z;
        Xt[(c + 3) * 68 + r] = v.w;
    }
    __syncthreads();

    unsigned long long accp[8];
    #pragma unroll
    for (int r = 0; r < 8; r++) accp[r] = 0ull;

    #pragma unroll 4
    for (int k = 0; k < DD; k++) {
        unsigned int wu = __float_as_uint(Ws[k * DD + col]);
        unsigned long long wp;
        asm("mov.b64 %0, {%1, %1};" : "=l"(wp) : "r"(wu));
        const ulonglong2* xp = reinterpret_cast<const ulonglong2*>(&Xt[k * 68 + rg * 16]);
        ulonglong2 a0 = xp[0], a1 = xp[1], a2 = xp[2], a3 = xp[3];
        asm("fma.rn.f32x2 %0, %1, %2, %0;" : "+l"(accp[0]) : "l"(a0.x), "l"(wp));
        asm("fma.rn.f32x2 %0, %1, %2, %0;" : "+l"(accp[1]) : "l"(a0.y), "l"(wp));
        asm("fma.rn.f32x2 %0, %1, %2, %0;" : "+l"(accp[2]) : "l"(a1.x), "l"(wp));
        asm("fma.rn.f32x2 %0, %1, %2, %0;" : "+l"(accp[3]) : "l"(a1.y), "l"(wp));
        asm("fma.rn.f32x2 %0, %1, %2, %0;" : "+l"(accp[4]) : "l"(a2.x), "l"(wp));
        asm("fma.rn.f32x2 %0, %1, %2, %0;" : "+l"(accp[5]) : "l"(a2.y), "l"(wp));
        asm("fma.rn.f32x2 %0, %1, %2, %0;" : "+l"(accp[6]) : "l"(a3.x), "l"(wp));
        asm("fma.rn.f32x2 %0, %1, %2, %0;" : "+l"(accp[7]) : "l"(a3.y), "l"(wp));
    }

    float ob = g_bc[col];
    float ps = 0.f, pss = 0.f;
    #pragma unroll
    for (int pr = 0; pr < 8; pr++) {
        unsigned int lo, hi;
        asm("mov.b64 {%0, %1}, %2;" : "=r"(lo), "=r"(hi) : "l"(accp[pr]));
        float v0 = __uint_as_float(lo), v1 = __uint_as_float(hi);
        int grow = r0 + rg * 16 + pr * 2;
        if (grow < NN) {
            float y = v0 + ob;
            if (outh) outh[(size_t)grow * DD + col] = __float2half(y);
            else      out[(size_t)grow * DD + col] = y;
            ps += y; pss += y * y;
        }
        if (grow + 1 < NN) {
            float y = v1 + ob;
            if (outh) outh[(size_t)(grow + 1) * DD + col] = __float2half(y);
            else      out[(size_t)(grow + 1) * DD + col] = y;
            ps += y; pss += y * y;
        }
    }
    sred[0][rg][col] = ps;
    sred[1][rg][col] = pss;
    __syncthreads();
    if (rg == 0) {
        float s  = sred[0][0][col] + sred[0][1][col] + sred[0][2][col] + sred[0][3][col];
        float ss = sred[1][0][col] + sred[1][1][col] + sred[1][2][col] + sred[1][3][col];
        atomicAdd(&g_stats[statsBase + col], s);
        atomicAdd(&g_stats[statsBase + 64 + col], ss);
    }
}

// ---------------- final BN+ReLU (coefficients computed per block) ---------
__global__ void k_bn_relu_out(const float* __restrict__ y, float* __restrict__ out,
                              const float* __restrict__ g, const float* __restrict__ bt) {
    __shared__ float s_sc[DD], s_sh[DD];
    if (threadIdx.x < DD) {
        int c = threadIdx.x;
        float mu  = g_stats[128 + c] * (1.0f / NN);
        float var = g_stats[192 + c] * (1.0f / NN) - mu * mu;
        float scv = g[c] * rsqrtf(var + EPSBN);
        s_sc[c] = scv;
        s_sh[c] = bt[c] - mu * scv;
    }
    __syncthreads();
    int i = blockIdx.x * blockDim.x + threadIdx.x;
    if (i < NN * DD) {
        int c = i & 63;
        out[i] = fmaxf(y[i] * s_sc[c] + s_sh[c], 0.f);
    }
}

// ---------------- launch ----------------
extern "C" void kernel_launch(void* const* d_in, const int* in_sizes, int n_in,
                              void* d_out, int out_size) {
    const float* x   = (const float*)d_in[0];
    const int*   src = (const int*)d_in[1];
    const int*   dst = src + NE;
    const float *W1  = (const float*)d_in[2],  *b1  = (const float*)d_in[3];
    const float *fw1 = (const float*)d_in[4],  *fb1 = (const float*)d_in[5];
    const float *g1  = (const float*)d_in[6],  *bt1 = (const float*)d_in[7];
    const float *W2  = (const float*)d_in[8],  *b2  = (const float*)d_in[9];
    const float *fw2 = (const float*)d_in[10], *fb2 = (const float*)d_in[11];
    const float *g2  = (const float*)d_in[12], *bt2 = (const float*)d_in[13];
    float* out = (float*)d_out;

    float *pagg, *py;
    __half* ph;
    cudaGetSymbolAddress((void**)&pagg, g_agg);
    cudaGetSymbolAddress((void**)&py,   g_y);
    cudaGetSymbolAddress((void**)&ph,   g_hsrc);

    const int T = 256;
    const int elemBlocks = (NN * DD + T - 1) / T;
    const int vecBlocks  = (NN * DD / 4 + T - 1) / T;
    const int gemmBlocks = (NN + 63) / 64;
    const int aggBlocks  = (NN + 15) / 16;
    dim3 gB(64, 4);
    dim3 cB(64, 16);

    // ---- CSR build (2 launches) ----
    k_x2h<<<vecBlocks, T>>>(x, dst);               // 1: x->half, zero deg, reset bars
    k_scan_scatter<<<NSM, 1024>>>(src, dst);       // 2: hist + scan + dinv + scatter

    // ---- layer 1 ----
    k_combine<<<1, cB>>>(W1, fw1, b1, fb1, 0);            // 3
    k_agg<<<aggBlocks, T>>>(pagg, 0, nullptr, nullptr);   // 4  <-- profiled
    k_gemm<<<gemmBlocks, gB>>>(pagg, nullptr, ph, 0);     // 5: y1 -> half

    // ---- layer 2 ----
    k_combine<<<1, cB>>>(W2, fw2, b2, fb2, 128);          // 6
    k_agg<<<aggBlocks, T>>>(pagg, 2, g1, bt1);            // 7: bnrelu on load
    k_gemm<<<gemmBlocks, gB>>>(pagg, py, nullptr, 128);   // 8
    k_bn_relu_out<<<elemBlocks, T>>>(py, out, g2, bt2);   // 9
}

// round 14
// speedup vs baseline: 1.1246x; 1.1246x over previous
#include <cuda_runtime.h>
#include <cuda_fp16.h>

#define NN 100000
#define NE 3200000
#define DD 64
#define EPSBN 1e-5f
#define NSM 148
#define NITEM ((NN + NSM - 1) / NSM)        // 676 items per block

// ---------------- scratch (no allocations allowed) ----------------
__device__ int    g_deg[NN];
__device__ int    g_off[NN + 1];
__device__ int    g_cursor[NN];
__device__ int    g_csum[NSM];
__device__ volatile int g_bar1;
__device__ volatile int g_bar2;
__device__ float  g_dinv[NN];
__device__ int2   g_entries[NE];           // {src, weight-bits}
__device__ __half g_hsrc[(size_t)NN * DD]; // half gather source (x, then y1)
__device__ float  g_agg[(size_t)NN * DD];
__device__ float  g_y[(size_t)NN * DD];
__device__ float  g_stats[4 * DD];         // [0..127] layer1, [128..255] layer2
__device__ float  g_wc[DD * DD];           // combined W@fw
__device__ float  g_bc[DD];                // combined bias

// ------- x -> half conversion (+ deg zero, + barrier reset) ---------------
__global__ void k_x2h(const float* __restrict__ x) {
    int i = blockIdx.x * blockDim.x + threadIdx.x;
    if (i < NN * DD / 4) {
        float4 v = reinterpret_cast<const float4*>(x)[i];
        __half2* o = reinterpret_cast<__half2*>(g_hsrc) + 2 * i;
        o[0] = __floats2half2_rn(v.x, v.y);
        o[1] = __floats2half2_rn(v.z, v.w);
    }
    if (i < NN) g_deg[i] = 0;
    if (i == 0) { g_bar1 = 0; g_bar2 = 0; }
}

// ---------------- histogram (own launch: full-width grid) -----------------
__global__ void k_hist(const int* __restrict__ dst) {
    int e = blockIdx.x * blockDim.x + threadIdx.x;
    if (e < NE) atomicAdd(&g_deg[dst[e]], 1);
}

// ---------------- fused scan + scatter (one wave, global spin barriers) ---
__device__ __forceinline__ void gbar(volatile int* bar) {
    __syncthreads();
    if (threadIdx.x == 0) {
        __threadfence();
        atomicAdd((int*)bar, 1);
        while (*bar < NSM) { }
    }
    __syncthreads();
}

__global__ void __launch_bounds__(1024) k_scan_scatter(const int* __restrict__ src,
                                                       const int* __restrict__ dst) {
    __shared__ int sh[1024];
    __shared__ int s_base;
    int b = blockIdx.x, t = threadIdx.x;
    int i = b * NITEM + t;
    int val = (t < NITEM && i < NN) ? g_deg[i] : 0;
    sh[t] = val;
    __syncthreads();
    #pragma unroll
    for (int o = 1; o < 1024; o <<= 1) {
        int xv = (t >= o) ? sh[t - o] : 0;
        __syncthreads();
        sh[t] += xv;
        __syncthreads();
    }
    if (t == 1023) g_csum[b] = sh[1023];
    int locex = sh[t] - val;                // exclusive within block

    gbar(&g_bar1);                          // all csum visible

    if (t == 0) {
        int s = 0;
        for (int j = 0; j < b; j++) s += g_csum[j];
        s_base = s;
    }
    __syncthreads();
    if (t < NITEM && i < NN) {
        int v = s_base + locex;
        g_off[i] = v;
        g_cursor[i] = v;
        g_dinv[i] = rsqrtf((float)(val + 1));   // +1 self loop
    }
    if (b == NSM - 1 && t == 0) g_off[NN] = NE;

    gbar(&g_bar2);                          // all offsets/dinv visible

    for (int e = b * 1024 + t; e < NE; e += NSM * 1024) {
        int s = src[e], d = dst[e];
        float w = g_dinv[s] * g_dinv[d];
        int pos = atomicAdd(&g_cursor[d], 1);
        g_entries[pos] = make_int2(s, __float_as_int(w));
    }
}

// ---------------- weight combine: Wc = W@fw, bc = b@fw + fb; zero stats ---
__global__ void k_combine(const float* __restrict__ W, const float* __restrict__ fw,
                          const float* __restrict__ b, const float* __restrict__ fb,
                          int statsBase) {
    int col = threadIdx.x;          // 0..63
    int rb  = threadIdx.y * 4;      // row base, y in 0..15
    float acc[4] = {0.f, 0.f, 0.f, 0.f};
    for (int k = 0; k < DD; k++) {
        float f = fw[k * DD + col];
        #pragma unroll
        for (int r = 0; r < 4; r++) acc[r] += W[(rb + r) * DD + k] * f;
    }
    #pragma unroll
    for (int r = 0; r < 4; r++) g_wc[(rb + r) * DD + col] = acc[r];
    if (threadIdx.y == 0) {
        float s = fb[col];
        for (int k = 0; k < DD; k++) s += b[k] * fw[k * DD + col];
        g_bc[col] = s;
    }
    if (threadIdx.y == 1) {
        g_stats[statsBase + col] = 0.f;
        g_stats[statsBase + 64 + col] = 0.f;
    }
}

// ---------------- helpers ----------------
__device__ __forceinline__ float4 h4f(uint2 r) {
    __half2 h0 = *reinterpret_cast<__half2*>(&r.x);
    __half2 h1 = *reinterpret_cast<__half2*>(&r.y);
    float2 f0 = __half22float2(h0);
    float2 f1 = __half22float2(h1);
    return make_float4(f0.x, f0.y, f1.x, f1.y);
}
__device__ __forceinline__ float4 bnr4(float4 v, float4 sc, float4 sh) {
    v.x = fmaxf(v.x * sc.x + sh.x, 0.f);
    v.y = fmaxf(v.y * sc.y + sh.y, 0.f);
    v.z = fmaxf(v.z * sc.z + sh.z, 0.f);
    v.w = fmaxf(v.w * sc.w + sh.w, 0.f);
    return v;
}

// ---------------- aggregation: gather over CSR (half rows), 16 thr/node ---
// paired int4 entry loads; 32-bit addressing; 6 blocks/SM requested
__global__ void __launch_bounds__(256, 6) k_agg(float* __restrict__ agg, int mode,
                                                const float* __restrict__ g,
                                                const float* __restrict__ bt) {
    __shared__ float s_sc[DD], s_sh[DD];
    if (mode == 2) {
        if (threadIdx.x < DD) {
            int c = threadIdx.x;
            float mu  = g_stats[c] * (1.0f / NN);
            float var = g_stats[64 + c] * (1.0f / NN) - mu * mu;
            float scv = g[c] * rsqrtf(var + EPSBN);
            s_sc[c] = scv;
            s_sh[c] = bt[c] - mu * scv;
        }
        __syncthreads();
    }

    int node = blockIdx.x * 16 + (threadIdx.x >> 4);
    int q = threadIdx.x & 15;                 // 8-byte (4-half) slice
    if (node >= NN) return;

    float4 sc = make_float4(1.f, 1.f, 1.f, 1.f);
    float4 sh = make_float4(0.f, 0.f, 0.f, 0.f);
    if (mode == 2) {
        sc = *reinterpret_cast<const float4*>(&s_sc[q * 4]);
        sh = *reinterpret_cast<const float4*>(&s_sh[q * 4]);
    }

    int beg = g_off[node];
    int end = g_off[node + 1];
    float di = g_dinv[node];
    float ww = di * di;

    const uint2* hs = reinterpret_cast<const uint2*>(g_hsrc);

    float4 a = h4f(hs[node * 16 + q]);
    if (mode == 2) a = bnr4(a, sc, sh);
    float4 acc = make_float4(ww * a.x, ww * a.y, ww * a.z, ww * a.w);

    int e = beg;
    if ((e & 1) && e < end) {
        int2 e0 = g_entries[e];
        float w0 = __int_as_float(e0.y);
        float4 v0 = h4f(hs[e0.x * 16 + q]);
        if (mode == 2) v0 = bnr4(v0, sc, sh);
        acc.x += w0 * v0.x; acc.y += w0 * v0.y;
        acc.z += w0 * v0.z; acc.w += w0 * v0.w;
        e++;
    }
    for (; e + 4 <= end; e += 4) {
        int4 p0 = *reinterpret_cast<const int4*>(g_entries + e);
        int4 p1 = *reinterpret_cast<const int4*>(g_entries + e + 2);
        float4 v0 = h4f(hs[p0.x * 16 + q]);
        float4 v1 = h4f(hs[p0.z * 16 + q]);
        float4 v2 = h4f(hs[p1.x * 16 + q]);
        float4 v3 = h4f(hs[p1.z * 16 + q]);
        if (mode == 2) {
            v0 = bnr4(v0, sc, sh);
            v1 = bnr4(v1, sc, sh);
            v2 = bnr4(v2, sc, sh);
            v3 = bnr4(v3, sc, sh);
        }
        float w0 = __int_as_float(p0.y), w1 = __int_as_float(p0.w);
        float w2 = __int_as_float(p1.y), w3 = __int_as_float(p1.w);
        acc.x += w0 * v0.x + w1 * v1.x + w2 * v2.x + w3 * v3.x;
        acc.y += w0 * v0.y + w1 * v1.y + w2 * v2.y + w3 * v3.y;
        acc.z += w0 * v0.z + w1 * v1.z + w2 * v2.z + w3 * v3.z;
        acc.w += w0 * v0.w + w1 * v1.w + w2 * v2.w + w3 * v3.w;
    }
    for (; e < end; e++) {
        int2 e0 = g_entries[e];
        float w0 = __int_as_float(e0.y);
        float4 v0 = h4f(hs[e0.x * 16 + q]);
        if (mode == 2) v0 = bnr4(v0, sc, sh);
        acc.x += w0 * v0.x;
        acc.y += w0 * v0.y;
        acc.z += w0 * v0.z;
        acc.w += w0 * v0.w;
    }
    *reinterpret_cast<float4*>(agg + node * 64 + q * 4) = acc;
}

// ---------------- GEMM: in[N,64] @ g_wc + g_bc -> out (fp32 or half) ------
// block(32,8): thread = (colpair c2, rowgroup rg of 8 rows); 2 cols x 8 rows.
// Xt k-row loads are warp-broadcast (all lanes same addr); Ws float2 coalesced.
__global__ void __launch_bounds__(256) k_gemm(const float* __restrict__ in,
                                              float* __restrict__ out,
                                              __half* __restrict__ outh,
                                              int statsBase) {
    __shared__ float Xt[DD * 68];              // [k][row], 64 rows + pad
    __shared__ float Ws[DD * DD];              // [k][col]
    __shared__ float sred[2][8][DD];

    const int c2  = threadIdx.x;               // 0..31
    const int rg  = threadIdx.y;               // 0..7
    const int tid = rg * 32 + c2;
    const int r0  = blockIdx.x * 64;

    #pragma unroll
    for (int it = 0; it < 4; it++) {
        int fi = (tid + it * 256) * 4;
        *reinterpret_cast<float4*>(&Ws[fi]) =
            *reinterpret_cast<const float4*>(&g_wc[fi]);
    }
    #pragma unroll
    for (int it = 0; it < 4; it++) {
        int fi = (tid + it * 256) * 4;
        int r = fi >> 6;
        int c = fi & 63;
        float4 v;
        if (r0 + r < NN)
            v = *reinterpret_cast<const float4*>(&in[(size_t)(r0 + r) * DD + c]);
        else
            v = make_float4(0.f, 0.f, 0.f, 0.f);
        Xt[(c + 0) * 68 + r] = v.x;
        Xt[(c + 1) * 68 + r] = v.y;
        Xt[(c + 2) * 68 + r] = v.z;
        Xt[(c + 3) * 68 + r] = v.w;
    }
    __syncthreads();

    // acc[c][p]: col c (2*c2+c), packed row pair p (rows rg*8+2p, +2p+1)
    unsigned long long acc[2][4];
    #pragma unroll
    for (int c = 0; c < 2; c++)
        #pragma unroll
        for (int p = 0; p < 4; p++) acc[c][p] = 0ull;

    #pragma unroll 4
    for (int k = 0; k < DD; k++) {
        const ulonglong2* xp =
            reinterpret_cast<const ulonglong2*>(&Xt[k * 68 + rg * 8]);
        ulonglong2 A0 = xp[0];                 // rows 0-1, 2-3 of group
        ulonglong2 A1 = xp[1];                 // rows 4-5, 6-7
        float2 wv = *reinterpret_cast<const float2*>(&Ws[k * DD + c2 * 2]);
        unsigned long long w0p, w1p;
        unsigned int w0u = __float_as_uint(wv.x);
        unsigned int w1u = __float_as_uint(wv.y);
        asm("mov.b64 %0, {%1, %1};" : "=l"(w0p) : "r"(w0u));
        asm("mov.b64 %0, {%1, %1};" : "=l"(w1p) : "r"(w1u));
        asm("fma.rn.f32x2 %0, %1, %2, %0;" : "+l"(acc[0][0]) : "l"(A0.x), "l"(w0p));
        asm("fma.rn.f32x2 %0, %1, %2, %0;" : "+l"(acc[0][1]) : "l"(A0.y), "l"(w0p));
        asm("fma.rn.f32x2 %0, %1, %2, %0;" : "+l"(acc[0][2]) : "l"(A1.x), "l"(w0p));
        asm("fma.rn.f32x2 %0, %1, %2, %0;" : "+l"(acc[0][3]) : "l"(A1.y), "l"(w0p));
        asm("fma.rn.f32x2 %0, %1, %2, %0;" : "+l"(acc[1][0]) : "l"(A0.x), "l"(w1p));
        asm("fma.rn.f32x2 %0, %1, %2, %0;" : "+l"(acc[1][1]) : "l"(A0.y), "l"(w1p));
        asm("fma.rn.f32x2 %0, %1, %2, %0;" : "+l"(acc[1][2]) : "l"(A1.x), "l"(w1p));
        asm("fma.rn.f32x2 %0, %1, %2, %0;" : "+l"(acc[1][3]) : "l"(A1.y), "l"(w1p));
    }

    float ob0 = g_bc[c2 * 2];
    float ob1 = g_bc[c2 * 2 + 1];
    float ps0 = 0.f, pss0 = 0.f, ps1 = 0.f, pss1 = 0.f;
    #pragma unroll
    for (int p = 0; p < 4; p++) {
        unsigned int l0, h0, l1, h1;
        asm("mov.b64 {%0, %1}, %2;" : "=r"(l0), "=r"(h0) : "l"(acc[0][p]));
        asm("mov.b64 {%0, %1}, %2;" : "=r"(l1), "=r"(h1) : "l"(acc[1][p]));
        int grow = r0 + rg * 8 + p * 2;
        float ya0 = __uint_as_float(l0) + ob0;   // row grow,   col0
        float ya1 = __uint_as_float(l1) + ob1;   // row grow,   col1
        float yb0 = __uint_as_float(h0) + ob0;   // row grow+1, col0
        float yb1 = __uint_as_float(h1) + ob1;   // row grow+1, col1
        if (grow < NN) {
            if (outh)
                *reinterpret_cast<__half2*>(outh + (size_t)grow * DD + c2 * 2) =
                    __floats2half2_rn(ya0, ya1);
            else
                *reinterpret_cast<float2*>(out + (size_t)grow * DD + c2 * 2) =
                    make_float2(ya0, ya1);
            ps0 += ya0; pss0 += ya0 * ya0;
            ps1 += ya1; pss1 += ya1 * ya1;
        }
        if (grow + 1 < NN) {
            if (outh)
                *reinterpret_cast<__half2*>(outh + (size_t)(grow + 1) * DD + c2 * 2) =
                    __floats2half2_rn(yb0, yb1);
            else
                *reinterpret_cast<float2*>(out + (size_t)(grow + 1) * DD + c2 * 2) =
                    make_float2(yb0, yb1);
            ps0 += yb0; pss0 += yb0 * yb0;
            ps1 += yb1; pss1 += yb1 * yb1;
        }
    }
    sred[0][rg][c2 * 2]     = ps0;
    sred[0][rg][c2 * 2 + 1] = ps1;
    sred[1][rg][c2 * 2]     = pss0;
    sred[1][rg][c2 * 2 + 1] = pss1;
    __syncthreads();
    if (rg == 0) {
        #pragma unroll
        for (int c = 0; c < 2; c++) {
            int col = c2 * 2 + c;
            float s = 0.f, ss = 0.f;
            #pragma unroll
            for (int r = 0; r < 8; r++) {
                s  += sred[0][r][col];
                ss += sred[1][r][col];
            }
            atomicAdd(&g_stats[statsBase + col], s);
            atomicAdd(&g_stats[statsBase + 64 + col], ss);
        }
    }
}

// ---------------- final BN+ReLU (coefficients computed per block) ---------
__global__ void k_bn_relu_out(const float* __restrict__ y, float* __restrict__ out,
                              const float* __restrict__ g, const float* __restrict__ bt) {
    __shared__ float s_sc[DD], s_sh[DD];
    if (threadIdx.x < DD) {
        int c = threadIdx.x;
        float mu  = g_stats[128 + c] * (1.0f / NN);
        float var = g_stats[192 + c] * (1.0f / NN) - mu * mu;
        float scv = g[c] * rsqrtf(var + EPSBN);
        s_sc[c] = scv;
        s_sh[c] = bt[c] - mu * scv;
    }
    __syncthreads();
    int i = blockIdx.x * blockDim.x + threadIdx.x;
    if (i < NN * DD) {
        int c = i & 63;
        out[i] = fmaxf(y[i] * s_sc[c] + s_sh[c], 0.f);
    }
}

// ---------------- launch ----------------
extern "C" void kernel_launch(void* const* d_in, const int* in_sizes, int n_in,
                              void* d_out, int out_size) {
    const float* x   = (const float*)d_in[0];
    const int*   src = (const int*)d_in[1];
    const int*   dst = src + NE;
    const float *W1  = (const float*)d_in[2],  *b1  = (const float*)d_in[3];
    const float *fw1 = (const float*)d_in[4],  *fb1 = (const float*)d_in[5];
    const float *g1  = (const float*)d_in[6],  *bt1 = (const float*)d_in[7];
    const float *W2  = (const float*)d_in[8],  *b2  = (const float*)d_in[9];
    const float *fw2 = (const float*)d_in[10], *fb2 = (const float*)d_in[11];
    const float *g2  = (const float*)d_in[12], *bt2 = (const float*)d_in[13];
    float* out = (float*)d_out;

    float *pagg, *py;
    __half* ph;
    cudaGetSymbolAddress((void**)&pagg, g_agg);
    cudaGetSymbolAddress((void**)&py,   g_y);
    cudaGetSymbolAddress((void**)&ph,   g_hsrc);

    const int T = 256;
    const int elemBlocks = (NN * DD + T - 1) / T;
    const int vecBlocks  = (NN * DD / 4 + T - 1) / T;
    const int edgeBlocks = (NE + T - 1) / T;
    const int gemmBlocks = (NN + 63) / 64;
    const int aggBlocks  = (NN + 15) / 16;
    dim3 gB(32, 8);
    dim3 cB(64, 16);

    // ---- CSR build ----
    k_x2h<<<vecBlocks, T>>>(x);                    // 1: x->half, zero deg, reset bars
    k_hist<<<edgeBlocks, T>>>(dst);                // 2: full-width histogram
    k_scan_scatter<<<NSM, 1024>>>(src, dst);       // 3: scan + dinv + scatter

    // ---- layer 1 ----
    k_agg<<<aggBlocks, T>>>(pagg, 0, nullptr, nullptr);   // 4  <-- profiled
    k_combine<<<1, cB>>>(W1, fw1, b1, fb1, 0);            // 5
    k_gemm<<<gemmBlocks, gB>>>(pagg, nullptr, ph, 0);     // 6: y1 -> half

    // ---- layer 2 ----
    k_combine<<<1, cB>>>(W2, fw2, b2, fb2, 128);          // 7
    k_agg<<<aggBlocks, T>>>(pagg, 2, g1, bt1);            // 8
    k_gemm<<<gemmBlocks, gB>>>(pagg, py, nullptr, 128);   // 9
    k_bn_relu_out<<<elemBlocks, T>>>(py, out, g2, bt2);   // 10
}

// round 15
// speedup vs baseline: 1.1604x; 1.0319x over previous
#include <cuda_runtime.h>
#include <cuda_fp16.h>

#define NN 100000
#define NE 3200000
#define DD 64
#define EPSBN 1e-5f
#define NSM 148
#define NITEM ((NN + NSM - 1) / NSM)        // 676 items per block

// ---------------- scratch (no allocations allowed) ----------------
__device__ int    g_deg[NN];
__device__ int    g_off[NN + 1];
__device__ int    g_cursor[NN];
__device__ int    g_csum[NSM];
__device__ volatile int g_bar1;
__device__ volatile int g_bar2;
__device__ float  g_dinv[NN];
__device__ int2   g_entries[NE];           // {src, weight-bits}
__device__ __half g_hsrc[(size_t)NN * DD]; // half gather source (x, then y1)
__device__ float  g_agg[(size_t)NN * DD];
__device__ float  g_y[(size_t)NN * DD];
__device__ float  g_stats[4 * DD];         // [0..127] layer1, [128..255] layer2
__device__ float  g_wc[DD * DD];           // combined W@fw
__device__ float  g_bc[DD];                // combined bias

// ------- x -> half conversion (+ deg zero, + barrier reset) ---------------
__global__ void k_x2h(const float* __restrict__ x) {
    int i = blockIdx.x * blockDim.x + threadIdx.x;
    if (i < NN * DD / 4) {
        float4 v = reinterpret_cast<const float4*>(x)[i];
        __half2* o = reinterpret_cast<__half2*>(g_hsrc) + 2 * i;
        o[0] = __floats2half2_rn(v.x, v.y);
        o[1] = __floats2half2_rn(v.z, v.w);
    }
    if (i < NN) g_deg[i] = 0;
    if (i == 0) { g_bar1 = 0; g_bar2 = 0; }
}

// ---------------- histogram (int4: 4 edges/thread) ------------------------
__global__ void k_hist(const int* __restrict__ dst) {
    int v = blockIdx.x * blockDim.x + threadIdx.x;
    if (v < NE / 4) {
        int4 d = reinterpret_cast<const int4*>(dst)[v];
        atomicAdd(&g_deg[d.x], 1);
        atomicAdd(&g_deg[d.y], 1);
        atomicAdd(&g_deg[d.z], 1);
        atomicAdd(&g_deg[d.w], 1);
    }
}

// ---------------- fused scan + scatter (one wave, global spin barriers) ---
__device__ __forceinline__ void gbar(volatile int* bar) {
    __syncthreads();
    if (threadIdx.x == 0) {
        __threadfence();
        atomicAdd((int*)bar, 1);
        while (*bar < NSM) { }
    }
    __syncthreads();
}

__global__ void __launch_bounds__(1024) k_scan_scatter(const int* __restrict__ src,
                                                       const int* __restrict__ dst) {
    __shared__ int sh[1024];
    __shared__ int s_base;
    int b = blockIdx.x, t = threadIdx.x;
    int i = b * NITEM + t;
    int val = (t < NITEM && i < NN) ? g_deg[i] : 0;
    sh[t] = val;
    __syncthreads();
    #pragma unroll
    for (int o = 1; o < 1024; o <<= 1) {
        int xv = (t >= o) ? sh[t - o] : 0;
        __syncthreads();
        sh[t] += xv;
        __syncthreads();
    }
    if (t == 1023) g_csum[b] = sh[1023];
    int locex = sh[t] - val;                // exclusive within block (saved in reg)

    gbar(&g_bar1);                          // all csum visible

    // parallel sum of csum[0..b) into s_base
    sh[t] = (t < b) ? g_csum[t] : 0;
    __syncthreads();
    #pragma unroll
    for (int o = 512; o > 0; o >>= 1) {
        if (t < o) sh[t] += sh[t + o];
        __syncthreads();
    }
    if (t == 0) s_base = sh[0];
    __syncthreads();

    if (t < NITEM && i < NN) {
        int v = s_base + locex;
        g_off[i] = v;
        g_cursor[i] = v;
        g_dinv[i] = rsqrtf((float)(val + 1));   // +1 self loop
    }
    if (b == NSM - 1 && t == 0) g_off[NN] = NE;

    gbar(&g_bar2);                          // all offsets/dinv visible

    // scatter: int4 loads = 4 edges per iteration
    const int4* src4 = reinterpret_cast<const int4*>(src);
    const int4* dst4 = reinterpret_cast<const int4*>(dst);
    for (int v = b * 1024 + t; v < NE / 4; v += NSM * 1024) {
        int4 s4 = src4[v];
        int4 d4 = dst4[v];
        float w;
        int pos;
        w = g_dinv[s4.x] * g_dinv[d4.x];
        pos = atomicAdd(&g_cursor[d4.x], 1);
        g_entries[pos] = make_int2(s4.x, __float_as_int(w));
        w = g_dinv[s4.y] * g_dinv[d4.y];
        pos = atomicAdd(&g_cursor[d4.y], 1);
        g_entries[pos] = make_int2(s4.y, __float_as_int(w));
        w = g_dinv[s4.z] * g_dinv[d4.z];
        pos = atomicAdd(&g_cursor[d4.z], 1);
        g_entries[pos] = make_int2(s4.z, __float_as_int(w));
        w = g_dinv[s4.w] * g_dinv[d4.w];
        pos = atomicAdd(&g_cursor[d4.w], 1);
        g_entries[pos] = make_int2(s4.w, __float_as_int(w));
    }
}

// ---------------- weight combine: Wc = W@fw, bc = b@fw + fb; zero stats ---
__global__ void k_combine(const float* __restrict__ W, const float* __restrict__ fw,
                          const float* __restrict__ b, const float* __restrict__ fb,
                          int statsBase) {
    int col = threadIdx.x;          // 0..63
    int rb  = threadIdx.y * 4;      // row base, y in 0..15
    float acc[4] = {0.f, 0.f, 0.f, 0.f};
    for (int k = 0; k < DD; k++) {
        float f = fw[k * DD + col];
        #pragma unroll
        for (int r = 0; r < 4; r++) acc[r] += W[(rb + r) * DD + k] * f;
    }
    #pragma unroll
    for (int r = 0; r < 4; r++) g_wc[(rb + r) * DD + col] = acc[r];
    if (threadIdx.y == 0) {
        float s = fb[col];
        for (int k = 0; k < DD; k++) s += b[k] * fw[k * DD + col];
        g_bc[col] = s;
    }
    if (threadIdx.y == 1) {
        g_stats[statsBase + col] = 0.f;
        g_stats[statsBase + 64 + col] = 0.f;
    }
}

// ---------------- helpers ----------------
__device__ __forceinline__ float4 h4f(uint2 r) {
    __half2 h0 = *reinterpret_cast<__half2*>(&r.x);
    __half2 h1 = *reinterpret_cast<__half2*>(&r.y);
    float2 f0 = __half22float2(h0);
    float2 f1 = __half22float2(h1);
    return make_float4(f0.x, f0.y, f1.x, f1.y);
}
__device__ __forceinline__ float4 bnr4(float4 v, float4 sc, float4 sh) {
    v.x = fmaxf(v.x * sc.x + sh.x, 0.f);
    v.y = fmaxf(v.y * sc.y + sh.y, 0.f);
    v.z = fmaxf(v.z * sc.z + sh.z, 0.f);
    v.w = fmaxf(v.w * sc.w + sh.w, 0.f);
    return v;
}

// ---------------- aggregation: gather over CSR (half rows), 16 thr/node ---
// MODE templated (0: raw, 2: bn+relu on load); entry loads software-pipelined
template <int MODE>
__global__ void __launch_bounds__(256, 6) k_agg(float* __restrict__ agg,
                                                const float* __restrict__ g,
                                                const float* __restrict__ bt) {
    __shared__ float s_sc[DD], s_sh[DD];
    if (MODE == 2) {
        if (threadIdx.x < DD) {
            int c = threadIdx.x;
            float mu  = g_stats[c] * (1.0f / NN);
            float var = g_stats[64 + c] * (1.0f / NN) - mu * mu;
            float scv = g[c] * rsqrtf(var + EPSBN);
            s_sc[c] = scv;
            s_sh[c] = bt[c] - mu * scv;
        }
        __syncthreads();
    }

    int node = blockIdx.x * 16 + (threadIdx.x >> 4);
    int q = threadIdx.x & 15;                 // 8-byte (4-half) slice
    if (node >= NN) return;

    float4 sc, sh;
    if (MODE == 2) {
        sc = *reinterpret_cast<const float4*>(&s_sc[q * 4]);
        sh = *reinterpret_cast<const float4*>(&s_sh[q * 4]);
    }

    int beg = g_off[node];
    int end = g_off[node + 1];
    float di = g_dinv[node];
    float ww = di * di;

    const uint2* hs = reinterpret_cast<const uint2*>(g_hsrc);

    float4 a = h4f(hs[node * 16 + q]);
    if (MODE == 2) a = bnr4(a, sc, sh);
    float4 acc = make_float4(ww * a.x, ww * a.y, ww * a.z, ww * a.w);

    int e = beg;
    if ((e & 1) && e < end) {                 // align to even for int4 pairs
        int2 e0 = g_entries[e];
        float w0 = __int_as_float(e0.y);
        float4 v0 = h4f(hs[e0.x * 16 + q]);
        if (MODE == 2) v0 = bnr4(v0, sc, sh);
        acc.x += w0 * v0.x; acc.y += w0 * v0.y;
        acc.z += w0 * v0.z; acc.w += w0 * v0.w;
        e++;
    }

    int nq = (end - e) >> 2;                  // 4-edge iterations
    if (nq > 0) {
        int4 p0 = *reinterpret_cast<const int4*>(g_entries + e);
        int4 p1 = *reinterpret_cast<const int4*>(g_entries + e + 2);
        for (int it = 1; it < nq; it++) {
            int4 n0 = *reinterpret_cast<const int4*>(g_entries + e + it * 4);
            int4 n1 = *reinterpret_cast<const int4*>(g_entries + e + it * 4 + 2);
            float4 v0 = h4f(hs[p0.x * 16 + q]);
            float4 v1 = h4f(hs[p0.z * 16 + q]);
            float4 v2 = h4f(hs[p1.x * 16 + q]);
            float4 v3 = h4f(hs[p1.z * 16 + q]);
            if (MODE == 2) {
                v0 = bnr4(v0, sc, sh); v1 = bnr4(v1, sc, sh);
                v2 = bnr4(v2, sc, sh); v3 = bnr4(v3, sc, sh);
            }
            float w0 = __int_as_float(p0.y), w1 = __int_as_float(p0.w);
            float w2 = __int_as_float(p1.y), w3 = __int_as_float(p1.w);
            acc.x += w0 * v0.x + w1 * v1.x + w2 * v2.x + w3 * v3.x;
            acc.y += w0 * v0.y + w1 * v1.y + w2 * v2.y + w3 * v3.y;
            acc.z += w0 * v0.z + w1 * v1.z + w2 * v2.z + w3 * v3.z;
            acc.w += w0 * v0.w + w1 * v1.w + w2 * v2.w + w3 * v3.w;
            p0 = n0; p1 = n1;
        }
        {
            float4 v0 = h4f(hs[p0.x * 16 + q]);
            float4 v1 = h4f(hs[p0.z * 16 + q]);
            float4 v2 = h4f(hs[p1.x * 16 + q]);
            float4 v3 = h4f(hs[p1.z * 16 + q]);
            if (MODE == 2) {
                v0 = bnr4(v0, sc, sh); v1 = bnr4(v1, sc, sh);
                v2 = bnr4(v2, sc, sh); v3 = bnr4(v3, sc, sh);
            }
            float w0 = __int_as_float(p0.y), w1 = __int_as_float(p0.w);
            float w2 = __int_as_float(p1.y), w3 = __int_as_float(p1.w);
            acc.x += w0 * v0.x + w1 * v1.x + w2 * v2.x + w3 * v3.x;
            acc.y += w0 * v0.y + w1 * v1.y + w2 * v2.y + w3 * v3.y;
            acc.z += w0 * v0.z + w1 * v1.z + w2 * v2.z + w3 * v3.z;
            acc.w += w0 * v0.w + w1 * v1.w + w2 * v2.w + w3 * v3.w;
        }
        e += nq * 4;
    }
    for (; e < end; e++) {
        int2 e0 = g_entries[e];
        float w0 = __int_as_float(e0.y);
        float4 v0 = h4f(hs[e0.x * 16 + q]);
        if (MODE == 2) v0 = bnr4(v0, sc, sh);
        acc.x += w0 * v0.x;
        acc.y += w0 * v0.y;
        acc.z += w0 * v0.z;
        acc.w += w0 * v0.w;
    }
    *reinterpret_cast<float4*>(agg + node * 64 + q * 4) = acc;
}

// ---------------- GEMM: in[N,64] @ g_wc + g_bc -> out (fp32 or half) ------
// block(32,8): thread = 2 cols x 8 rows; FFMA2 inner loop.
__global__ void __launch_bounds__(256) k_gemm(const float* __restrict__ in,
                                              float* __restrict__ out,
                                              __half* __restrict__ outh,
                                              int statsBase) {
    __shared__ float Xt[DD * 68];              // [k][row], 64 rows + pad
    __shared__ float Ws[DD * DD];              // [k][col]
    __shared__ float sred[2][8][DD];

    const int c2  = threadIdx.x;               // 0..31
    const int rg  = threadIdx.y;               // 0..7
    const int tid = rg * 32 + c2;
    const int r0  = blockIdx.x * 64;

    #pragma unroll
    for (int it = 0; it < 4; it++) {
        int fi = (tid + it * 256) * 4;
        *reinterpret_cast<float4*>(&Ws[fi]) =
            *reinterpret_cast<const float4*>(&g_wc[fi]);
    }
    #pragma unroll
    for (int it = 0; it < 4; it++) {
        int fi = (tid + it * 256) * 4;
        int r = fi >> 6;
        int c = fi & 63;
        float4 v;
        if (r0 + r < NN)
            v = *reinterpret_cast<const float4*>(&in[(size_t)(r0 + r) * DD + c]);
        else
            v = make_float4(0.f, 0.f, 0.f, 0.f);
        Xt[(c + 0) * 68 + r] = v.x;
        Xt[(c + 1) * 68 + r] = v.y;
        Xt[(c + 2) * 68 + r] = v.z;
        Xt[(c + 3) * 68 + r] = v.w;
    }
    __syncthreads();

    unsigned long long acc[2][4];
    #pragma unroll
    for (int c = 0; c < 2; c++)
        #pragma unroll
        for (int p = 0; p < 4; p++) acc[c][p] = 0ull;

    #pragma unroll 4
    for (int k = 0; k < DD; k++) {
        const ulonglong2* xp =
            reinterpret_cast<const ulonglong2*>(&Xt[k * 68 + rg * 8]);
        ulonglong2 A0 = xp[0];
        ulonglong2 A1 = xp[1];
        float2 wv = *reinterpret_cast<const float2*>(&Ws[k * DD + c2 * 2]);
        unsigned long long w0p, w1p;
        unsigned int w0u = __float_as_uint(wv.x);
        unsigned int w1u = __float_as_uint(wv.y);
        asm("mov.b64 %0, {%1, %1};" : "=l"(w0p) : "r"(w0u));
        asm("mov.b64 %0, {%1, %1};" : "=l"(w1p) : "r"(w1u));
        asm("fma.rn.f32x2 %0, %1, %2, %0;" : "+l"(acc[0][0]) : "l"(A0.x), "l"(w0p));
        asm("fma.rn.f32x2 %0, %1, %2, %0;" : "+l"(acc[0][1]) : "l"(A0.y), "l"(w0p));
        asm("fma.rn.f32x2 %0, %1, %2, %0;" : "+l"(acc[0][2]) : "l"(A1.x), "l"(w0p));
        asm("fma.rn.f32x2 %0, %1, %2, %0;" : "+l"(acc[0][3]) : "l"(A1.y), "l"(w0p));
        asm("fma.rn.f32x2 %0, %1, %2, %0;" : "+l"(acc[1][0]) : "l"(A0.x), "l"(w1p));
        asm("fma.rn.f32x2 %0, %1, %2, %0;" : "+l"(acc[1][1]) : "l"(A0.y), "l"(w1p));
        asm("fma.rn.f32x2 %0, %1, %2, %0;" : "+l"(acc[1][2]) : "l"(A1.x), "l"(w1p));
        asm("fma.rn.f32x2 %0, %1, %2, %0;" : "+l"(acc[1][3]) : "l"(A1.y), "l"(w1p));
    }

    float ob0 = g_bc[c2 * 2];
    float ob1 = g_bc[c2 * 2 + 1];
    float ps0 = 0.f, pss0 = 0.f, ps1 = 0.f, pss1 = 0.f;
    #pragma unroll
    for (int p = 0; p < 4; p++) {
        unsigned int l0, h0, l1, h1;
        asm("mov.b64 {%0, %1}, %2;" : "=r"(l0), "=r"(h0) : "l"(acc[0][p]));
        asm("mov.b64 {%0, %1}, %2;" : "=r"(l1), "=r"(h1) : "l"(acc[1][p]));
        int grow = r0 + rg * 8 + p * 2;
        float ya0 = __uint_as_float(l0) + ob0;
        float ya1 = __uint_as_float(l1) + ob1;
        float yb0 = __uint_as_float(h0) + ob0;
        float yb1 = __uint_as_float(h1) + ob1;
        if (grow < NN) {
            if (outh)
                *reinterpret_cast<__half2*>(outh + (size_t)grow * DD + c2 * 2) =
                    __floats2half2_rn(ya0, ya1);
            else
                *reinterpret_cast<float2*>(out + (size_t)grow * DD + c2 * 2) =
                    make_float2(ya0, ya1);
            ps0 += ya0; pss0 += ya0 * ya0;
            ps1 += ya1; pss1 += ya1 * ya1;
        }
        if (grow + 1 < NN) {
            if (outh)
                *reinterpret_cast<__half2*>(outh + (size_t)(grow + 1) * DD + c2 * 2) =
                    __floats2half2_rn(yb0, yb1);
            else
                *reinterpret_cast<float2*>(out + (size_t)(grow + 1) * DD + c2 * 2) =
                    make_float2(yb0, yb1);
            ps0 += yb0; pss0 += yb0 * yb0;
            ps1 += yb1; pss1 += yb1 * yb1;
        }
    }
    sred[0][rg][c2 * 2]     = ps0;
    sred[0][rg][c2 * 2 + 1] = ps1;
    sred[1][rg][c2 * 2]     = pss0;
    sred[1][rg][c2 * 2 + 1] = pss1;
    __syncthreads();
    if (rg == 0) {
        #pragma unroll
        for (int c = 0; c < 2; c++) {
            int col = c2 * 2 + c;
            float s = 0.f, ss = 0.f;
            #pragma unroll
            for (int r = 0; r < 8; r++) {
                s  += sred[0][r][col];
                ss += sred[1][r][col];
            }
            atomicAdd(&g_stats[statsBase + col], s);
            atomicAdd(&g_stats[statsBase + 64 + col], ss);
        }
    }
}

// ---------------- final BN+ReLU (coefficients computed per block) ---------
__global__ void k_bn_relu_out(const float* __restrict__ y, float* __restrict__ out,
                              const float* __restrict__ g, const float* __restrict__ bt) {
    __shared__ float s_sc[DD], s_sh[DD];
    if (threadIdx.x < DD) {
        int c = threadIdx.x;
        float mu  = g_stats[128 + c] * (1.0f / NN);
        float var = g_stats[192 + c] * (1.0f / NN) - mu * mu;
        float scv = g[c] * rsqrtf(var + EPSBN);
        s_sc[c] = scv;
        s_sh[c] = bt[c] - mu * scv;
    }
    __syncthreads();
    int i = blockIdx.x * blockDim.x + threadIdx.x;
    if (i < NN * DD) {
        int c = i & 63;
        out[i] = fmaxf(y[i] * s_sc[c] + s_sh[c], 0.f);
    }
}

// ---------------- launch ----------------
extern "C" void kernel_launch(void* const* d_in, const int* in_sizes, int n_in,
                              void* d_out, int out_size) {
    const float* x   = (const float*)d_in[0];
    const int*   src = (const int*)d_in[1];
    const int*   dst = src + NE;
    const float *W1  = (const float*)d_in[2],  *b1  = (const float*)d_in[3];
    const float *fw1 = (const float*)d_in[4],  *fb1 = (const float*)d_in[5];
    const float *g1  = (const float*)d_in[6],  *bt1 = (const float*)d_in[7];
    const float *W2  = (const float*)d_in[8],  *b2  = (const float*)d_in[9];
    const float *fw2 = (const float*)d_in[10], *fb2 = (const float*)d_in[11];
    const float *g2  = (const float*)d_in[12], *bt2 = (const float*)d_in[13];
    float* out = (float*)d_out;

    float *pagg, *py;
    __half* ph;
    cudaGetSymbolAddress((void**)&pagg, g_agg);
    cudaGetSymbolAddress((void**)&py,   g_y);
    cudaGetSymbolAddress((void**)&ph,   g_hsrc);

    const int T = 256;
    const int elemBlocks = (NN * DD + T - 1) / T;
    const int vecBlocks  = (NN * DD / 4 + T - 1) / T;
    const int histBlocks = (NE / 4 + T - 1) / T;
    const int gemmBlocks = (NN + 63) / 64;
    const int aggBlocks  = (NN + 15) / 16;
    dim3 gB(32, 8);
    dim3 cB(64, 16);

    // ---- CSR build ----
    k_x2h<<<vecBlocks, T>>>(x);                    // 1
    k_hist<<<histBlocks, T>>>(dst);                // 2
    k_scan_scatter<<<NSM, 1024>>>(src, dst);       // 3

    // ---- layer 1 ----
    k_agg<0><<<aggBlocks, T>>>(pagg, nullptr, nullptr);   // 4  <-- profiled
    k_combine<<<1, cB>>>(W1, fw1, b1, fb1, 0);            // 5
    k_gemm<<<gemmBlocks, gB>>>(pagg, nullptr, ph, 0);     // 6: y1 -> half

    // ---- layer 2 ----
    k_combine<<<1, cB>>>(W2, fw2, b2, fb2, 128);          // 7
    k_agg<2><<<aggBlocks, T>>>(pagg, g1, bt1);            // 8
    k_gemm<<<gemmBlocks, gB>>>(pagg, py, nullptr, 128);   // 9
    k_bn_relu_out<<<elemBlocks, T>>>(py, out, g2, bt2);   // 10
}

// round 16
// speedup vs baseline: 1.1806x; 1.0174x over previous
#include <cuda_runtime.h>
#include <cuda_fp16.h>

#define NN 100000
#define NE 3200000
#define DD 64
#define EPSBN 1e-5f
#define NSM 148
#define NITEM ((NN + NSM - 1) / NSM)        // 676 items per block

// ---------------- scratch (no allocations allowed) ----------------
// NOTE: g_deg / g_bar1 / g_bar2 are zero on first call (static zero-init)
// and re-zeroed at the tail of k_bn_relu_out, so every call starts clean.
__device__ int    g_deg[NN];
__device__ int    g_off[NN + 1];
__device__ int    g_cursor[NN];
__device__ int    g_csum[NSM];
__device__ volatile int g_bar1;
__device__ volatile int g_bar2;
__device__ float  g_dinv[NN];
__device__ int2   g_entries[NE];           // {src, weight-bits}
__device__ __half g_hsrc[(size_t)NN * DD]; // half gather source (x, then y1)
__device__ float  g_agg[(size_t)NN * DD];
__device__ float  g_y[(size_t)NN * DD];
__device__ float  g_stats[4 * DD];         // [0..127] layer1, [128..255] layer2
__device__ float  g_wc[DD * DD];           // combined W@fw
__device__ float  g_bc[DD];                // combined bias

// ------- x -> half conversion + histogram (g_deg pre-zeroed) --------------
__global__ void k_x2h(const float* __restrict__ x, const int* __restrict__ dst) {
    int i = blockIdx.x * blockDim.x + threadIdx.x;
    if (i < NN * DD / 4) {
        float4 v = reinterpret_cast<const float4*>(x)[i];
        __half2* o = reinterpret_cast<__half2*>(g_hsrc) + 2 * i;
        o[0] = __floats2half2_rn(v.x, v.y);
        o[1] = __floats2half2_rn(v.z, v.w);
    }
    if (i < NE / 4) {
        int4 d = reinterpret_cast<const int4*>(dst)[i];
        atomicAdd(&g_deg[d.x], 1);
        atomicAdd(&g_deg[d.y], 1);
        atomicAdd(&g_deg[d.z], 1);
        atomicAdd(&g_deg[d.w], 1);
    }
}

// ---------------- fused scan + scatter (one wave, global spin barriers) ---
__device__ __forceinline__ void gbar(volatile int* bar) {
    __syncthreads();
    if (threadIdx.x == 0) {
        __threadfence();
        atomicAdd((int*)bar, 1);
        while (*bar < NSM) { }
    }
    __syncthreads();
}

__global__ void __launch_bounds__(1024) k_scan_scatter(const int* __restrict__ src,
                                                       const int* __restrict__ dst) {
    __shared__ int sh[1024];
    __shared__ int s_base;
    int b = blockIdx.x, t = threadIdx.x;
    int i = b * NITEM + t;
    int val = (t < NITEM && i < NN) ? g_deg[i] : 0;
    sh[t] = val;
    __syncthreads();
    #pragma unroll
    for (int o = 1; o < 1024; o <<= 1) {
        int xv = (t >= o) ? sh[t - o] : 0;
        __syncthreads();
        sh[t] += xv;
        __syncthreads();
    }
    if (t == 1023) g_csum[b] = sh[1023];
    int locex = sh[t] - val;                // exclusive within block

    gbar(&g_bar1);                          // all csum visible

    sh[t] = (t < b) ? g_csum[t] : 0;
    __syncthreads();
    #pragma unroll
    for (int o = 512; o > 0; o >>= 1) {
        if (t < o) sh[t] += sh[t + o];
        __syncthreads();
    }
    if (t == 0) s_base = sh[0];
    __syncthreads();

    if (t < NITEM && i < NN) {
        int v = s_base + locex;
        g_off[i] = v;
        g_cursor[i] = v;
        g_dinv[i] = rsqrtf((float)(val + 1));   // +1 self loop
    }
    if (b == NSM - 1 && t == 0) g_off[NN] = NE;

    gbar(&g_bar2);                          // all offsets/dinv visible

    const int4* src4 = reinterpret_cast<const int4*>(src);
    const int4* dst4 = reinterpret_cast<const int4*>(dst);
    for (int v = b * 1024 + t; v < NE / 4; v += NSM * 1024) {
        int4 s4 = src4[v];
        int4 d4 = dst4[v];
        float w;
        int pos;
        w = g_dinv[s4.x] * g_dinv[d4.x];
        pos = atomicAdd(&g_cursor[d4.x], 1);
        g_entries[pos] = make_int2(s4.x, __float_as_int(w));
        w = g_dinv[s4.y] * g_dinv[d4.y];
        pos = atomicAdd(&g_cursor[d4.y], 1);
        g_entries[pos] = make_int2(s4.y, __float_as_int(w));
        w = g_dinv[s4.z] * g_dinv[d4.z];
        pos = atomicAdd(&g_cursor[d4.z], 1);
        g_entries[pos] = make_int2(s4.z, __float_as_int(w));
        w = g_dinv[s4.w] * g_dinv[d4.w];
        pos = atomicAdd(&g_cursor[d4.w], 1);
        g_entries[pos] = make_int2(s4.w, __float_as_int(w));
    }
}

// ---------------- weight combine: Wc = W@fw, bc = b@fw + fb; zero stats ---
__global__ void k_combine(const float* __restrict__ W, const float* __restrict__ fw,
                          const float* __restrict__ b, const float* __restrict__ fb,
                          int statsBase) {
    int col = threadIdx.x;          // 0..63
    int rb  = threadIdx.y * 4;      // row base, y in 0..15
    float acc[4] = {0.f, 0.f, 0.f, 0.f};
    for (int k = 0; k < DD; k++) {
        float f = fw[k * DD + col];
        #pragma unroll
        for (int r = 0; r < 4; r++) acc[r] += W[(rb + r) * DD + k] * f;
    }
    #pragma unroll
    for (int r = 0; r < 4; r++) g_wc[(rb + r) * DD + col] = acc[r];
    if (threadIdx.y == 0) {
        float s = fb[col];
        for (int k = 0; k < DD; k++) s += b[k] * fw[k * DD + col];
        g_bc[col] = s;
    }
    if (threadIdx.y == 1) {
        g_stats[statsBase + col] = 0.f;
        g_stats[statsBase + 64 + col] = 0.f;
    }
}

// ---------------- helpers ----------------
__device__ __forceinline__ float4 h4f(uint2 r) {
    __half2 h0 = *reinterpret_cast<__half2*>(&r.x);
    __half2 h1 = *reinterpret_cast<__half2*>(&r.y);
    float2 f0 = __half22float2(h0);
    float2 f1 = __half22float2(h1);
    return make_float4(f0.x, f0.y, f1.x, f1.y);
}
__device__ __forceinline__ float4 bnr4(float4 v, float4 sc, float4 sh) {
    v.x = fmaxf(v.x * sc.x + sh.x, 0.f);
    v.y = fmaxf(v.y * sc.y + sh.y, 0.f);
    v.z = fmaxf(v.z * sc.z + sh.z, 0.f);
    v.w = fmaxf(v.w * sc.w + sh.w, 0.f);
    return v;
}

// ---------------- aggregation: gather over CSR (half rows), 16 thr/node ---
// 8 nodes/block (128 thr) for finer load balance; entry loads pipelined
template <int MODE>
__global__ void __launch_bounds__(128, 12) k_agg(float* __restrict__ agg,
                                                 const float* __restrict__ g,
                                                 const float* __restrict__ bt) {
    __shared__ float s_sc[DD], s_sh[DD];
    if (MODE == 2) {
        if (threadIdx.x < DD) {
            int c = threadIdx.x;
            float mu  = g_stats[c] * (1.0f / NN);
            float var = g_stats[64 + c] * (1.0f / NN) - mu * mu;
            float scv = g[c] * rsqrtf(var + EPSBN);
            s_sc[c] = scv;
            s_sh[c] = bt[c] - mu * scv;
        }
        __syncthreads();
    }

    int node = blockIdx.x * 8 + (threadIdx.x >> 4);
    int q = threadIdx.x & 15;                 // 8-byte (4-half) slice
    if (node >= NN) return;

    float4 sc, sh;
    if (MODE == 2) {
        sc = *reinterpret_cast<const float4*>(&s_sc[q * 4]);
        sh = *reinterpret_cast<const float4*>(&s_sh[q * 4]);
    }

    int beg = g_off[node];
    int end = g_off[node + 1];
    float di = g_dinv[node];
    float ww = di * di;

    const uint2* hs = reinterpret_cast<const uint2*>(g_hsrc);

    float4 a = h4f(hs[node * 16 + q]);
    if (MODE == 2) a = bnr4(a, sc, sh);
    float4 acc = make_float4(ww * a.x, ww * a.y, ww * a.z, ww * a.w);

    int e = beg;
    if ((e & 1) && e < end) {                 // align to even for int4 pairs
        int2 e0 = g_entries[e];
        float w0 = __int_as_float(e0.y);
        float4 v0 = h4f(hs[e0.x * 16 + q]);
        if (MODE == 2) v0 = bnr4(v0, sc, sh);
        acc.x += w0 * v0.x; acc.y += w0 * v0.y;
        acc.z += w0 * v0.z; acc.w += w0 * v0.w;
        e++;
    }

    int nq = (end - e) >> 2;                  // 4-edge iterations
    if (nq > 0) {
        int4 p0 = *reinterpret_cast<const int4*>(g_entries + e);
        int4 p1 = *reinterpret_cast<const int4*>(g_entries + e + 2);
        for (int it = 1; it < nq; it++) {
            int4 n0 = *reinterpret_cast<const int4*>(g_entries + e + it * 4);
            int4 n1 = *reinterpret_cast<const int4*>(g_entries + e + it * 4 + 2);
            float4 v0 = h4f(hs[p0.x * 16 + q]);
            float4 v1 = h4f(hs[p0.z * 16 + q]);
            float4 v2 = h4f(hs[p1.x * 16 + q]);
            float4 v3 = h4f(hs[p1.z * 16 + q]);
            if (MODE == 2) {
                v0 = bnr4(v0, sc, sh); v1 = bnr4(v1, sc, sh);
                v2 = bnr4(v2, sc, sh); v3 = bnr4(v3, sc, sh);
            }
            float w0 = __int_as_float(p0.y), w1 = __int_as_float(p0.w);
            float w2 = __int_as_float(p1.y), w3 = __int_as_float(p1.w);
            acc.x += w0 * v0.x + w1 * v1.x + w2 * v2.x + w3 * v3.x;
            acc.y += w0 * v0.y + w1 * v1.y + w2 * v2.y + w3 * v3.y;
            acc.z += w0 * v0.z + w1 * v1.z + w2 * v2.z + w3 * v3.z;
            acc.w += w0 * v0.w + w1 * v1.w + w2 * v2.w + w3 * v3.w;
            p0 = n0; p1 = n1;
        }
        {
            float4 v0 = h4f(hs[p0.x * 16 + q]);
            float4 v1 = h4f(hs[p0.z * 16 + q]);
            float4 v2 = h4f(hs[p1.x * 16 + q]);
            float4 v3 = h4f(hs[p1.z * 16 + q]);
            if (MODE == 2) {
                v0 = bnr4(v0, sc, sh); v1 = bnr4(v1, sc, sh);
                v2 = bnr4(v2, sc, sh); v3 = bnr4(v3, sc, sh);
            }
            float w0 = __int_as_float(p0.y), w1 = __int_as_float(p0.w);
            float w2 = __int_as_float(p1.y), w3 = __int_as_float(p1.w);
            acc.x += w0 * v0.x + w1 * v1.x + w2 * v2.x + w3 * v3.x;
            acc.y += w0 * v0.y + w1 * v1.y + w2 * v2.y + w3 * v3.y;
            acc.z += w0 * v0.z + w1 * v1.z + w2 * v2.z + w3 * v3.z;
            acc.w += w0 * v0.w + w1 * v1.w + w2 * v2.w + w3 * v3.w;
        }
        e += nq * 4;
    }
    for (; e < end; e++) {
        int2 e0 = g_entries[e];
        float w0 = __int_as_float(e0.y);
        float4 v0 = h4f(hs[e0.x * 16 + q]);
        if (MODE == 2) v0 = bnr4(v0, sc, sh);
        acc.x += w0 * v0.x;
        acc.y += w0 * v0.y;
        acc.z += w0 * v0.z;
        acc.w += w0 * v0.w;
    }
    *reinterpret_cast<float4*>(agg + node * 64 + q * 4) = acc;
}

// ---------------- GEMM: in[N,64] @ g_wc + g_bc -> out (fp32 or half) ------
__global__ void __launch_bounds__(256) k_gemm(const float* __restrict__ in,
                                              float* __restrict__ out,
                                              __half* __restrict__ outh,
                                              int statsBase) {
    __shared__ float Xt[DD * 68];              // [k][row], 64 rows + pad
    __shared__ float Ws[DD * DD];              // [k][col]
    __shared__ float sred[2][8][DD];

    const int c2  = threadIdx.x;               // 0..31
    const int rg  = threadIdx.y;               // 0..7
    const int tid = rg * 32 + c2;
    const int r0  = blockIdx.x * 64;

    #pragma unroll
    for (int it = 0; it < 4; it++) {
        int fi = (tid + it * 256) * 4;
        *reinterpret_cast<float4*>(&Ws[fi]) =
            *reinterpret_cast<const float4*>(&g_wc[fi]);
    }
    #pragma unroll
    for (int it = 0; it < 4; it++) {
        int fi = (tid + it * 256) * 4;
        int r = fi >> 6;
        int c = fi & 63;
        float4 v;
        if (r0 + r < NN)
            v = *reinterpret_cast<const float4*>(&in[(size_t)(r0 + r) * DD + c]);
        else
            v = make_float4(0.f, 0.f, 0.f, 0.f);
        Xt[(c + 0) * 68 + r] = v.x;
        Xt[(c + 1) * 68 + r] = v.y;
        Xt[(c + 2) * 68 + r] = v.z;
        Xt[(c + 3) * 68 + r] = v.w;
    }
    __syncthreads();

    unsigned long long acc[2][4];
    #pragma unroll
    for (int c = 0; c < 2; c++)
        #pragma unroll
        for (int p = 0; p < 4; p++) acc[c][p] = 0ull;

    #pragma unroll 4
    for (int k = 0; k < DD; k++) {
        const ulonglong2* xp =
            reinterpret_cast<const ulonglong2*>(&Xt[k * 68 + rg * 8]);
        ulonglong2 A0 = xp[0];
        ulonglong2 A1 = xp[1];
        float2 wv = *reinterpret_cast<const float2*>(&Ws[k * DD + c2 * 2]);
        unsigned long long w0p, w1p;
        unsigned int w0u = __float_as_uint(wv.x);
        unsigned int w1u = __float_as_uint(wv.y);
        asm("mov.b64 %0, {%1, %1};" : "=l"(w0p) : "r"(w0u));
        asm("mov.b64 %0, {%1, %1};" : "=l"(w1p) : "r"(w1u));
        asm("fma.rn.f32x2 %0, %1, %2, %0;" : "+l"(acc[0][0]) : "l"(A0.x), "l"(w0p));
        asm("fma.rn.f32x2 %0, %1, %2, %0;" : "+l"(acc[0][1]) : "l"(A0.y), "l"(w0p));
        asm("fma.rn.f32x2 %0, %1, %2, %0;" : "+l"(acc[0][2]) : "l"(A1.x), "l"(w0p));
        asm("fma.rn.f32x2 %0, %1, %2, %0;" : "+l"(acc[0][3]) : "l"(A1.y), "l"(w0p));
        asm("fma.rn.f32x2 %0, %1, %2, %0;" : "+l"(acc[1][0]) : "l"(A0.x), "l"(w1p));
        asm("fma.rn.f32x2 %0, %1, %2, %0;" : "+l"(acc[1][1]) : "l"(A0.y), "l"(w1p));
        asm("fma.rn.f32x2 %0, %1, %2, %0;" : "+l"(acc[1][2]) : "l"(A1.x), "l"(w1p));
        asm("fma.rn.f32x2 %0, %1, %2, %0;" : "+l"(acc[1][3]) : "l"(A1.y), "l"(w1p));
    }

    float ob0 = g_bc[c2 * 2];
    float ob1 = g_bc[c2 * 2 + 1];
    float ps0 = 0.f, pss0 = 0.f, ps1 = 0.f, pss1 = 0.f;
    #pragma unroll
    for (int p = 0; p < 4; p++) {
        unsigned int l0, h0, l1, h1;
        asm("mov.b64 {%0, %1}, %2;" : "=r"(l0), "=r"(h0) : "l"(acc[0][p]));
        asm("mov.b64 {%0, %1}, %2;" : "=r"(l1), "=r"(h1) : "l"(acc[1][p]));
        int grow = r0 + rg * 8 + p * 2;
        float ya0 = __uint_as_float(l0) + ob0;
        float ya1 = __uint_as_float(l1) + ob1;
        float yb0 = __uint_as_float(h0) + ob0;
        float yb1 = __uint_as_float(h1) + ob1;
        if (grow < NN) {
            if (outh)
                *reinterpret_cast<__half2*>(outh + (size_t)grow * DD + c2 * 2) =
                    __floats2half2_rn(ya0, ya1);
            else
                *reinterpret_cast<float2*>(out + (size_t)grow * DD + c2 * 2) =
                    make_float2(ya0, ya1);
            ps0 += ya0; pss0 += ya0 * ya0;
            ps1 += ya1; pss1 += ya1 * ya1;
        }
        if (grow + 1 < NN) {
            if (outh)
                *reinterpret_cast<__half2*>(outh + (size_t)(grow + 1) * DD + c2 * 2) =
                    __floats2half2_rn(yb0, yb1);
            else
                *reinterpret_cast<float2*>(out + (size_t)(grow + 1) * DD + c2 * 2) =
                    make_float2(yb0, yb1);
            ps0 += yb0; pss0 += yb0 * yb0;
            ps1 += yb1; pss1 += yb1 * yb1;
        }
    }
    sred[0][rg][c2 * 2]     = ps0;
    sred[0][rg][c2 * 2 + 1] = ps1;
    sred[1][rg][c2 * 2]     = pss0;
    sred[1][rg][c2 * 2 + 1] = pss1;
    __syncthreads();
    if (rg == 0) {
        #pragma unroll
        for (int c = 0; c < 2; c++) {
            int col = c2 * 2 + c;
            float s = 0.f, ss = 0.f;
            #pragma unroll
            for (int r = 0; r < 8; r++) {
                s  += sred[0][r][col];
                ss += sred[1][r][col];
            }
            atomicAdd(&g_stats[statsBase + col], s);
            atomicAdd(&g_stats[statsBase + 64 + col], ss);
        }
    }
}

// -------- final BN+ReLU + state reset for the NEXT call -------------------
__global__ void k_bn_relu_out(const float* __restrict__ y, float* __restrict__ out,
                              const float* __restrict__ g, const float* __restrict__ bt) {
    __shared__ float s_sc[DD], s_sh[DD];
    if (threadIdx.x < DD) {
        int c = threadIdx.x;
        float mu  = g_stats[128 + c] * (1.0f / NN);
        float var = g_stats[192 + c] * (1.0f / NN) - mu * mu;
        float scv = g[c] * rsqrtf(var + EPSBN);
        s_sc[c] = scv;
        s_sh[c] = bt[c] - mu * scv;
    }
    __syncthreads();
    int i = blockIdx.x * blockDim.x + threadIdx.x;
    if (i < NN * DD) {
        int c = i & 63;
        out[i] = fmaxf(y[i] * s_sc[c] + s_sh[c], 0.f);
    }
    if (i < NN) g_deg[i] = 0;                 // reset for next call
    if (i == 0) { g_bar1 = 0; g_bar2 = 0; }
}

// ---------------- launch ----------------
extern "C" void kernel_launch(void* const* d_in, const int* in_sizes, int n_in,
                              void* d_out, int out_size) {
    const float* x   = (const float*)d_in[0];
    const int*   src = (const int*)d_in[1];
    const int*   dst = src + NE;
    const float *W1  = (const float*)d_in[2],  *b1  = (const float*)d_in[3];
    const float *fw1 = (const float*)d_in[4],  *fb1 = (const float*)d_in[5];
    const float *g1  = (const float*)d_in[6],  *bt1 = (const float*)d_in[7];
    const float *W2  = (const float*)d_in[8],  *b2  = (const float*)d_in[9];
    const float *fw2 = (const float*)d_in[10], *fb2 = (const float*)d_in[11];
    const float *g2  = (const float*)d_in[12], *bt2 = (const float*)d_in[13];
    float* out = (float*)d_out;

    float *pagg, *py;
    __half* ph;
    cudaGetSymbolAddress((void**)&pagg, g_agg);
    cudaGetSymbolAddress((void**)&py,   g_y);
    cudaGetSymbolAddress((void**)&ph,   g_hsrc);

    const int T = 256;
    const int elemBlocks = (NN * DD + T - 1) / T;
    const int vecBlocks  = (NN * DD / 4 + T - 1) / T;
    const int gemmBlocks = (NN + 63) / 64;
    const int aggBlocks  = (NN + 7) / 8;
    dim3 gB(32, 8);
    dim3 cB(64, 16);

    // ---- CSR build ----
    k_x2h<<<vecBlocks, T>>>(x, dst);               // 1: convert + histogram
    k_scan_scatter<<<NSM, 1024>>>(src, dst);       // 2

    // ---- layer 1 ----
    k_agg<0><<<aggBlocks, 128>>>(pagg, nullptr, nullptr); // 3
    k_combine<<<1, cB>>>(W1, fw1, b1, fb1, 0);            // 4  <-- profiled slot
    k_gemm<<<gemmBlocks, gB>>>(pagg, nullptr, ph, 0);     // 5: y1 -> half

    // ---- layer 2 ----
    k_combine<<<1, cB>>>(W2, fw2, b2, fb2, 128);          // 6
    k_agg<2><<<aggBlocks, 128>>>(pagg, g1, bt1);          // 7
    k_gemm<<<gemmBlocks, gB>>>(pagg, py, nullptr, 128);   // 8
    k_bn_relu_out<<<elemBlocks, T>>>(py, out, g2, bt2);   // 9: + state reset
}

// round 17
// speedup vs baseline: 1.2904x; 1.0930x over previous
#include <cuda_runtime.h>
#include <cuda_fp16.h>

#define NN 100000
#define NE 3200000
#define DD 64
#define EPSBN 1e-5f
#define NSM 148
#define NITEM ((NN + NSM - 1) / NSM)        // 676 items per block

// ---------------- scratch (no allocations allowed) ----------------
// g_deg / g_bar1 / g_bar2: zero at first call (static init), re-zeroed at
// the tail of k_bn_relu_out so every graph replay starts clean.
__device__ int    g_deg[NN];
__device__ int    g_off[NN + 1];
__device__ int    g_cursor[NN];
__device__ int    g_csum[NSM];
__device__ volatile int g_bar1;
__device__ volatile int g_bar2;
__device__ float  g_dinv[NN];
__device__ int2   g_entries[NE];           // {src, weight-bits}
__device__ __half g_hsrc[(size_t)NN * DD]; // half gather source (x, then y1)
__device__ float  g_agg[(size_t)NN * DD];
__device__ float  g_y[(size_t)NN * DD];
__device__ float  g_stats[4 * DD];         // [0..127] layer1, [128..255] layer2
__device__ float  g_wc[2 * DD * DD];       // combined W@fw, per layer
__device__ float  g_bc[2 * DD];            // combined bias, per layer

// ------- x -> half conversion + histogram (g_deg pre-zeroed) --------------
__global__ void k_x2h(const float* __restrict__ x, const int* __restrict__ dst) {
    int i = blockIdx.x * blockDim.x + threadIdx.x;
    if (i < NN * DD / 4) {
        float4 v = reinterpret_cast<const float4*>(x)[i];
        __half2* o = reinterpret_cast<__half2*>(g_hsrc) + 2 * i;
        o[0] = __floats2half2_rn(v.x, v.y);
        o[1] = __floats2half2_rn(v.z, v.w);
    }
    if (i < NE / 4) {
        int4 d = reinterpret_cast<const int4*>(dst)[i];
        atomicAdd(&g_deg[d.x], 1);
        atomicAdd(&g_deg[d.y], 1);
        atomicAdd(&g_deg[d.z], 1);
        atomicAdd(&g_deg[d.w], 1);
    }
}

// ---------------- fused scan + scatter (one wave, global spin barriers) ---
__device__ __forceinline__ void gbar(volatile int* bar) {
    __syncthreads();
    if (threadIdx.x == 0) {
        __threadfence();
        atomicAdd((int*)bar, 1);
        while (*bar < NSM) { }
    }
    __syncthreads();
}

__global__ void __launch_bounds__(1024) k_scan_scatter(const int* __restrict__ src,
                                                       const int* __restrict__ dst) {
    __shared__ int sh[1024];
    __shared__ int s_base;
    int b = blockIdx.x, t = threadIdx.x;
    int i = b * NITEM + t;
    int val = (t < NITEM && i < NN) ? g_deg[i] : 0;
    sh[t] = val;
    __syncthreads();
    #pragma unroll
    for (int o = 1; o < 1024; o <<= 1) {
        int xv = (t >= o) ? sh[t - o] : 0;
        __syncthreads();
        sh[t] += xv;
        __syncthreads();
    }
    if (t == 1023) g_csum[b] = sh[1023];
    int locex = sh[t] - val;                // exclusive within block

    gbar(&g_bar1);                          // all csum visible

    sh[t] = (t < b) ? g_csum[t] : 0;
    __syncthreads();
    #pragma unroll
    for (int o = 512; o > 0; o >>= 1) {
        if (t < o) sh[t] += sh[t + o];
        __syncthreads();
    }
    if (t == 0) s_base = sh[0];
    __syncthreads();

    if (t < NITEM && i < NN) {
        int v = s_base + locex;
        g_off[i] = v;
        g_cursor[i] = v;
        g_dinv[i] = rsqrtf((float)(val + 1));   // +1 self loop
    }
    if (b == NSM - 1 && t == 0) g_off[NN] = NE;

    gbar(&g_bar2);                          // all offsets/dinv visible

    const int4* src4 = reinterpret_cast<const int4*>(src);
    const int4* dst4 = reinterpret_cast<const int4*>(dst);
    for (int v = b * 1024 + t; v < NE / 4; v += NSM * 1024) {
        int4 s4 = src4[v];
        int4 d4 = dst4[v];
        float w;
        int pos;
        w = g_dinv[s4.x] * g_dinv[d4.x];
        pos = atomicAdd(&g_cursor[d4.x], 1);
        g_entries[pos] = make_int2(s4.x, __float_as_int(w));
        w = g_dinv[s4.y] * g_dinv[d4.y];
        pos = atomicAdd(&g_cursor[d4.y], 1);
        g_entries[pos] = make_int2(s4.y, __float_as_int(w));
        w = g_dinv[s4.z] * g_dinv[d4.z];
        pos = atomicAdd(&g_cursor[d4.z], 1);
        g_entries[pos] = make_int2(s4.z, __float_as_int(w));
        w = g_dinv[s4.w] * g_dinv[d4.w];
        pos = atomicAdd(&g_cursor[d4.w], 1);
        g_entries[pos] = make_int2(s4.w, __float_as_int(w));
    }
}

// ------- weight combine BOTH layers: Wc = W@fw, bc = b@fw + fb ------------
// grid = 2 (blockIdx.x = layer), block (64,16) = 1024 threads.
// W, fw staged to smem via coalesced float4 loads; inner loop is
// LDS-broadcast + FMA (no DRAM latency chain). Also zeroes stats.
__global__ void __launch_bounds__(1024) k_combine2(
        const float* __restrict__ W1, const float* __restrict__ fw1,
        const float* __restrict__ b1, const float* __restrict__ fb1,
        const float* __restrict__ W2, const float* __restrict__ fw2,
        const float* __restrict__ b2, const float* __restrict__ fb2) {
    __shared__ float Wsm[DD * DD];
    __shared__ float Fsm[DD * DD];
    int L = blockIdx.x;
    const float* W  = L ? W2  : W1;
    const float* fw = L ? fw2 : fw1;
    const float* b  = L ? b2  : b1;
    const float* fb = L ? fb2 : fb1;

    int col = threadIdx.x;          // 0..63
    int ty  = threadIdx.y;          // 0..15
    int tid = ty * 64 + col;        // 0..1023

    *reinterpret_cast<float4*>(&Wsm[tid * 4]) =
        *reinterpret_cast<const float4*>(&W[tid * 4]);
    *reinterpret_cast<float4*>(&Fsm[tid * 4]) =
        *reinterpret_cast<const float4*>(&fw[tid * 4]);
    __syncthreads();

    int rb = ty * 4;
    float acc[4] = {0.f, 0.f, 0.f, 0.f};
    #pragma unroll 4
    for (int k = 0; k < DD; k++) {
        float f = Fsm[k * DD + col];
        #pragma unroll
        for (int r = 0; r < 4; r++) acc[r] += Wsm[(rb + r) * DD + k] * f;
    }
    #pragma unroll
    for (int r = 0; r < 4; r++) g_wc[L * DD * DD + (rb + r) * DD + col] = acc[r];
    if (ty == 0) {
        float s = fb[col];
        #pragma unroll 4
        for (int k = 0; k < DD; k++) s += b[k] * Fsm[k * DD + col];
        g_bc[L * DD + col] = s;
    }
    if (ty == 1) {
        g_stats[L * 128 + col] = 0.f;
        g_stats[L * 128 + 64 + col] = 0.f;
    }
}

// ---------------- helpers ----------------
__device__ __forceinline__ float4 h4f(uint2 r) {
    __half2 h0 = *reinterpret_cast<__half2*>(&r.x);
    __half2 h1 = *reinterpret_cast<__half2*>(&r.y);
    float2 f0 = __half22float2(h0);
    float2 f1 = __half22float2(h1);
    return make_float4(f0.x, f0.y, f1.x, f1.y);
}
__device__ __forceinline__ float4 bnr4(float4 v, float4 sc, float4 sh) {
    v.x = fmaxf(v.x * sc.x + sh.x, 0.f);
    v.y = fmaxf(v.y * sc.y + sh.y, 0.f);
    v.z = fmaxf(v.z * sc.z + sh.z, 0.f);
    v.w = fmaxf(v.w * sc.w + sh.w, 0.f);
    return v;
}

// ---------------- aggregation: gather over CSR (half rows), 16 thr/node ---
template <int MODE>
__global__ void __launch_bounds__(128, 12) k_agg(float* __restrict__ agg,
                                                 const float* __restrict__ g,
                                                 const float* __restrict__ bt) {
    __shared__ float s_sc[DD], s_sh[DD];
    if (MODE == 2) {
        if (threadIdx.x < DD) {
            int c = threadIdx.x;
            float mu  = g_stats[c] * (1.0f / NN);
            float var = g_stats[64 + c] * (1.0f / NN) - mu * mu;
            float scv = g[c] * rsqrtf(var + EPSBN);
            s_sc[c] = scv;
            s_sh[c] = bt[c] - mu * scv;
        }
        __syncthreads();
    }

    int node = blockIdx.x * 8 + (threadIdx.x >> 4);
    int q = threadIdx.x & 15;                 // 8-byte (4-half) slice
    if (node >= NN) return;

    float4 sc, sh;
    if (MODE == 2) {
        sc = *reinterpret_cast<const float4*>(&s_sc[q * 4]);
        sh = *reinterpret_cast<const float4*>(&s_sh[q * 4]);
    }

    int beg = g_off[node];
    int end = g_off[node + 1];
    float di = g_dinv[node];
    float ww = di * di;

    const uint2* hs = reinterpret_cast<const uint2*>(g_hsrc);

    float4 a = h4f(hs[node * 16 + q]);
    if (MODE == 2) a = bnr4(a, sc, sh);
    float4 acc = make_float4(ww * a.x, ww * a.y, ww * a.z, ww * a.w);

    int e = beg;
    if ((e & 1) && e < end) {                 // align to even for int4 pairs
        int2 e0 = g_entries[e];
        float w0 = __int_as_float(e0.y);
        float4 v0 = h4f(hs[e0.x * 16 + q]);
        if (MODE == 2) v0 = bnr4(v0, sc, sh);
        acc.x += w0 * v0.x; acc.y += w0 * v0.y;
        acc.z += w0 * v0.z; acc.w += w0 * v0.w;
        e++;
    }

    int nq = (end - e) >> 2;                  // 4-edge iterations
    if (nq > 0) {
        int4 p0 = *reinterpret_cast<const int4*>(g_entries + e);
        int4 p1 = *reinterpret_cast<const int4*>(g_entries + e + 2);
        for (int it = 1; it < nq; it++) {
            int4 n0 = *reinterpret_cast<const int4*>(g_entries + e + it * 4);
            int4 n1 = *reinterpret_cast<const int4*>(g_entries + e + it * 4 + 2);
            float4 v0 = h4f(hs[p0.x * 16 + q]);
            float4 v1 = h4f(hs[p0.z * 16 + q]);
            float4 v2 = h4f(hs[p1.x * 16 + q]);
            float4 v3 = h4f(hs[p1.z * 16 + q]);
            if (MODE == 2) {
                v0 = bnr4(v0, sc, sh); v1 = bnr4(v1, sc, sh);
                v2 = bnr4(v2, sc, sh); v3 = bnr4(v3, sc, sh);
            }
            float w0 = __int_as_float(p0.y), w1 = __int_as_float(p0.w);
            float w2 = __int_as_float(p1.y), w3 = __int_as_float(p1.w);
            acc.x += w0 * v0.x + w1 * v1.x + w2 * v2.x + w3 * v3.x;
            acc.y += w0 * v0.y + w1 * v1.y + w2 * v2.y + w3 * v3.y;
            acc.z += w0 * v0.z + w1 * v1.z + w2 * v2.z + w3 * v3.z;
            acc.w += w0 * v0.w + w1 * v1.w + w2 * v2.w + w3 * v3.w;
            p0 = n0; p1 = n1;
        }
        {
            float4 v0 = h4f(hs[p0.x * 16 + q]);
            float4 v1 = h4f(hs[p0.z * 16 + q]);
            float4 v2 = h4f(hs[p1.x * 16 + q]);
            float4 v3 = h4f(hs[p1.z * 16 + q]);
            if (MODE == 2) {
                v0 = bnr4(v0, sc, sh); v1 = bnr4(v1, sc, sh);
                v2 = bnr4(v2, sc, sh); v3 = bnr4(v3, sc, sh);
            }
            float w0 = __int_as_float(p0.y), w1 = __int_as_float(p0.w);
            float w2 = __int_as_float(p1.y), w3 = __int_as_float(p1.w);
            acc.x += w0 * v0.x + w1 * v1.x + w2 * v2.x + w3 * v3.x;
            acc.y += w0 * v0.y + w1 * v1.y + w2 * v2.y + w3 * v3.y;
            acc.z += w0 * v0.z + w1 * v1.z + w2 * v2.z + w3 * v3.z;
            acc.w += w0 * v0.w + w1 * v1.w + w2 * v2.w + w3 * v3.w;
        }
        e += nq * 4;
    }
    for (; e < end; e++) {
        int2 e0 = g_entries[e];
        float w0 = __int_as_float(e0.y);
        float4 v0 = h4f(hs[e0.x * 16 + q]);
        if (MODE == 2) v0 = bnr4(v0, sc, sh);
        acc.x += w0 * v0.x;
        acc.y += w0 * v0.y;
        acc.z += w0 * v0.z;
        acc.w += w0 * v0.w;
    }
    *reinterpret_cast<float4*>(agg + node * 64 + q * 4) = acc;
}

// ---------------- GEMM: in[N,64] @ g_wc[L] + g_bc[L] -> out ---------------
__global__ void __launch_bounds__(256) k_gemm(const float* __restrict__ in,
                                              float* __restrict__ out,
                                              __half* __restrict__ outh,
                                              int L) {
    __shared__ float Xt[DD * 68];              // [k][row], 64 rows + pad
    __shared__ float Ws[DD * DD];              // [k][col]
    __shared__ float sred[2][8][DD];

    const int c2  = threadIdx.x;               // 0..31
    const int rg  = threadIdx.y;               // 0..7
    const int tid = rg * 32 + c2;
    const int r0  = blockIdx.x * 64;

    #pragma unroll
    for (int it = 0; it < 4; it++) {
        int fi = (tid + it * 256) * 4;
        *reinterpret_cast<float4*>(&Ws[fi]) =
            *reinterpret_cast<const float4*>(&g_wc[L * DD * DD + fi]);
    }
    #pragma unroll
    for (int it = 0; it < 4; it++) {
        int fi = (tid + it * 256) * 4;
        int r = fi >> 6;
        int c = fi & 63;
        float4 v;
        if (r0 + r < NN)
            v = *reinterpret_cast<const float4*>(&in[(size_t)(r0 + r) * DD + c]);
        else
            v = make_float4(0.f, 0.f, 0.f, 0.f);
        Xt[(c + 0) * 68 + r] = v.x;
        Xt[(c + 1) * 68 + r] = v.y;
        Xt[(c + 2) * 68 + r] = v.z;
        Xt[(c + 3) * 68 + r] = v.w;
    }
    __syncthreads();

    unsigned long long acc[2][4];
    #pragma unroll
    for (int c = 0; c < 2; c++)
        #pragma unroll
        for (int p = 0; p < 4; p++) acc[c][p] = 0ull;

    #pragma unroll 4
    for (int k = 0; k < DD; k++) {
        const ulonglong2* xp =
            reinterpret_cast<const ulonglong2*>(&Xt[k * 68 + rg * 8]);
        ulonglong2 A0 = xp[0];
        ulonglong2 A1 = xp[1];
        float2 wv = *reinterpret_cast<const float2*>(&Ws[k * DD + c2 * 2]);
        unsigned long long w0p, w1p;
        unsigned int w0u = __float_as_uint(wv.x);
        unsigned int w1u = __float_as_uint(wv.y);
        asm("mov.b64 %0, {%1, %1};" : "=l"(w0p) : "r"(w0u));
        asm("mov.b64 %0, {%1, %1};" : "=l"(w1p) : "r"(w1u));
        asm("fma.rn.f32x2 %0, %1, %2, %0;" : "+l"(acc[0][0]) : "l"(A0.x), "l"(w0p));
        asm("fma.rn.f32x2 %0, %1, %2, %0;" : "+l"(acc[0][1]) : "l"(A0.y), "l"(w0p));
        asm("fma.rn.f32x2 %0, %1, %2, %0;" : "+l"(acc[0][2]) : "l"(A1.x), "l"(w0p));
        asm("fma.rn.f32x2 %0, %1, %2, %0;" : "+l"(acc[0][3]) : "l"(A1.y), "l"(w0p));
        asm("fma.rn.f32x2 %0, %1, %2, %0;" : "+l"(acc[1][0]) : "l"(A0.x), "l"(w1p));
        asm("fma.rn.f32x2 %0, %1, %2, %0;" : "+l"(acc[1][1]) : "l"(A0.y), "l"(w1p));
        asm("fma.rn.f32x2 %0, %1, %2, %0;" : "+l"(acc[1][2]) : "l"(A1.x), "l"(w1p));
        asm("fma.rn.f32x2 %0, %1, %2, %0;" : "+l"(acc[1][3]) : "l"(A1.y), "l"(w1p));
    }

    float ob0 = g_bc[L * DD + c2 * 2];
    float ob1 = g_bc[L * DD + c2 * 2 + 1];
    float ps0 = 0.f, pss0 = 0.f, ps1 = 0.f, pss1 = 0.f;
    #pragma unroll
    for (int p = 0; p < 4; p++) {
        unsigned int l0, h0, l1, h1;
        asm("mov.b64 {%0, %1}, %2;" : "=r"(l0), "=r"(h0) : "l"(acc[0][p]));
        asm("mov.b64 {%0, %1}, %2;" : "=r"(l1), "=r"(h1) : "l"(acc[1][p]));
        int grow = r0 + rg * 8 + p * 2;
        float ya0 = __uint_as_float(l0) + ob0;
        float ya1 = __uint_as_float(l1) + ob1;
        float yb0 = __uint_as_float(h0) + ob0;
        float yb1 = __uint_as_float(h1) + ob1;
        if (grow < NN) {
            if (outh)
                *reinterpret_cast<__half2*>(outh + (size_t)grow * DD + c2 * 2) =
                    __floats2half2_rn(ya0, ya1);
            else
                *reinterpret_cast<float2*>(out + (size_t)grow * DD + c2 * 2) =
                    make_float2(ya0, ya1);
            ps0 += ya0; pss0 += ya0 * ya0;
            ps1 += ya1; pss1 += ya1 * ya1;
        }
        if (grow + 1 < NN) {
            if (outh)
                *reinterpret_cast<__half2*>(outh + (size_t)(grow + 1) * DD + c2 * 2) =
                    __floats2half2_rn(yb0, yb1);
            else
                *reinterpret_cast<float2*>(out + (size_t)(grow + 1) * DD + c2 * 2) =
                    make_float2(yb0, yb1);
            ps0 += yb0; pss0 += yb0 * yb0;
            ps1 += yb1; pss1 += yb1 * yb1;
        }
    }
    sred[0][rg][c2 * 2]     = ps0;
    sred[0][rg][c2 * 2 + 1] = ps1;
    sred[1][rg][c2 * 2]     = pss0;
    sred[1][rg][c2 * 2 + 1] = pss1;
    __syncthreads();
    if (rg == 0) {
        #pragma unroll
        for (int c = 0; c < 2; c++) {
            int col = c2 * 2 + c;
            float s = 0.f, ss = 0.f;
            #pragma unroll
            for (int r = 0; r < 8; r++) {
                s  += sred[0][r][col];
                ss += sred[1][r][col];
            }
            atomicAdd(&g_stats[L * 128 + col], s);
            atomicAdd(&g_stats[L * 128 + 64 + col], ss);
        }
    }
}

// -------- final BN+ReLU + state reset for the NEXT call -------------------
__global__ void k_bn_relu_out(const float* __restrict__ y, float* __restrict__ out,
                              const float* __restrict__ g, const float* __restrict__ bt) {
    __shared__ float s_sc[DD], s_sh[DD];
    if (threadIdx.x < DD) {
        int c = threadIdx.x;
        float mu  = g_stats[128 + c] * (1.0f / NN);
        float var = g_stats[192 + c] * (1.0f / NN) - mu * mu;
        float scv = g[c] * rsqrtf(var + EPSBN);
        s_sc[c] = scv;
        s_sh[c] = bt[c] - mu * scv;
    }
    __syncthreads();
    int i = blockIdx.x * blockDim.x + threadIdx.x;
    if (i < NN * DD) {
        int c = i & 63;
        out[i] = fmaxf(y[i] * s_sc[c] + s_sh[c], 0.f);
    }
    if (i < NN) g_deg[i] = 0;                 // reset for next call
    if (i == 0) { g_bar1 = 0; g_bar2 = 0; }
}

// ---------------- launch ----------------
extern "C" void kernel_launch(void* const* d_in, const int* in_sizes, int n_in,
                              void* d_out, int out_size) {
    const float* x   = (const float*)d_in[0];
    const int*   src = (const int*)d_in[1];
    const int*   dst = src + NE;
    const float *W1  = (const float*)d_in[2],  *b1  = (const float*)d_in[3];
    const float *fw1 = (const float*)d_in[4],  *fb1 = (const float*)d_in[5];
    const float *g1  = (const float*)d_in[6],  *bt1 = (const float*)d_in[7];
    const float *W2  = (const float*)d_in[8],  *b2  = (const float*)d_in[9];
    const float *fw2 = (const float*)d_in[10], *fb2 = (const float*)d_in[11];
    const float *g2  = (const float*)d_in[12], *bt2 = (const float*)d_in[13];
    float* out = (float*)d_out;

    float *pagg, *py;
    __half* ph;
    cudaGetSymbolAddress((void**)&pagg, g_agg);
    cudaGetSymbolAddress((void**)&py,   g_y);
    cudaGetSymbolAddress((void**)&ph,   g_hsrc);

    const int T = 256;
    const int elemBlocks = (NN * DD + T - 1) / T;
    const int vecBlocks  = (NN * DD / 4 + T - 1) / T;
    const int gemmBlocks = (NN + 63) / 64;
    const int aggBlocks  = (NN + 7) / 8;
    dim3 gB(32, 8);
    dim3 cB(64, 16);

    // ---- CSR build + both weight combines ----
    k_x2h<<<vecBlocks, T>>>(x, dst);               // 1: convert + histogram
    k_combine2<<<2, cB>>>(W1, fw1, b1, fb1,
                          W2, fw2, b2, fb2);       // 2: both layers' Wc/bc + stats
    k_scan_scatter<<<NSM, 1024>>>(src, dst);       // 3

    // ---- layer 1 ----
    k_agg<0><<<aggBlocks, 128>>>(pagg, nullptr, nullptr); // 4  <-- profiled
    k_gemm<<<gemmBlocks, gB>>>(pagg, nullptr, ph, 0);     // 5: y1 -> half

    // ---- layer 2 ----
    k_agg<2><<<aggBlocks, 128>>>(pagg, g1, bt1);          // 6
    k_gemm<<<gemmBlocks, gB>>>(pagg, py, nullptr, 1);     // 7
    k_bn_relu_out<<<elemBlocks, T>>>(py, out, g2, bt2);   // 8: + state reset
}